// round 1
// baseline (speedup 1.0000x reference)
#include <cuda_runtime.h>
#include <cuda_bf16.h>

// ---------------- problem constants ----------------
#define BATCH   256          // windows*batch
#define NTOK    343          // tokens per window
#define DIM     256
#define HEADS   8
#define HD      32
#define NWIN    64
#define SCALE   0.17677669529663687f   // 1/sqrt(32)

#define MROWS   (BATCH*NTOK)           // 87808
#define KSTRIDE 356                    // smem row stride for k^T / v^T (== 4 mod 32)
#define PSTRIDE 344                    // p-buffer / bias row stride (mult of 4, >= 343)

// ---------------- scratch (device globals; no allocations allowed) ----------------
__device__ float g_q [BATCH*HEADS*NTOK*HD];          // [b][h][n][d]   (scale folded in)
__device__ float g_kT[BATCH*HEADS*HD*NTOK];          // [b][h][d][n]
__device__ float g_vT[BATCH*HEADS*HD*NTOK];          // [b][h][d][n]
__device__ float g_ao[MROWS*DIM];                    // attention output [b*n][h*32+d]
__device__ float g_bm[(size_t)NWIN*HEADS*NTOK*PSTRIDE]; // fused bias+mask, padded rows

// ============================================================================
// Kernel 0: fuse relative-position bias + mask into g_bm[wh][i][PSTRIDE]
// ============================================================================
__global__ void bias_prep(const float* __restrict__ mask,
                          const float* __restrict__ table,
                          const int*   __restrict__ rel)
{
    int i  = blockIdx.x;            // row 0..342
    int wh = blockIdx.y;            // 0..511
    int w = wh >> 3, h = wh & 7;
    const float* mrow = mask + ((size_t)w*NTOK + i)*NTOK;
    const int*   rrow = rel  + i*NTOK;
    float*       orow = g_bm + ((size_t)wh*NTOK + i)*PSTRIDE;
    for (int j = threadIdx.x; j < PSTRIDE; j += blockDim.x) {
        float v = 0.f;
        if (j < NTOK) v = mrow[j] + table[rrow[j]*HEADS + h];
        orow[j] = v;
    }
}

// ============================================================================
// Tiled fp32 GEMM: C = A[M x 256] * W[256 x LDB] (+bias), custom epilogues.
// BM=BN=128, BK=16, 256 threads, 8x8 per thread.
// ============================================================================
#define BM 128
#define BN 128
#define BKK 16

__global__ __launch_bounds__(256)
void qkv_gemm(const float* __restrict__ X,
              const float* __restrict__ W,
              const float* __restrict__ Bias)
{
    __shared__ float Ast[BKK][BM];   // A transposed
    __shared__ float Bs [BKK][BN];
    const int ldb = 3*DIM;           // 768
    int tid = threadIdx.x;
    int tx = tid & 15, ty = tid >> 4;
    int m0 = blockIdx.x * BM, n0 = blockIdx.y * BN;
    float c[8][8] = {};

    for (int k0 = 0; k0 < DIM; k0 += BKK) {
        #pragma unroll
        for (int u = 0; u < 2; u++) {
            int f = tid*2 + u;
            int ar = f >> 2, ac = (f & 3) * 4;
            float4 av = *(const float4*)(X + (size_t)(m0 + ar)*DIM + k0 + ac);
            Ast[ac+0][ar] = av.x; Ast[ac+1][ar] = av.y;
            Ast[ac+2][ar] = av.z; Ast[ac+3][ar] = av.w;
            int br = f >> 5, bc = (f & 31) * 4;
            *(float4*)(&Bs[br][bc]) =
                *(const float4*)(W + (size_t)(k0 + br)*ldb + n0 + bc);
        }
        __syncthreads();
        #pragma unroll
        for (int k = 0; k < BKK; k++) {
            float4 a0 = *(float4*)(&Ast[k][ty*8]);
            float4 a1 = *(float4*)(&Ast[k][ty*8+4]);
            float4 b0 = *(float4*)(&Bs [k][tx*8]);
            float4 b1 = *(float4*)(&Bs [k][tx*8+4]);
            float a[8] = {a0.x,a0.y,a0.z,a0.w,a1.x,a1.y,a1.z,a1.w};
            float b[8] = {b0.x,b0.y,b0.z,b0.w,b1.x,b1.y,b1.z,b1.w};
            #pragma unroll
            for (int i = 0; i < 8; i++)
                #pragma unroll
                for (int j = 0; j < 8; j++)
                    c[i][j] += a[i]*b[j];
        }
        __syncthreads();
    }

    // epilogue: scatter into q (scaled), kT, vT
    int colbase = n0 + tx*8;
    float bv[8];
    #pragma unroll
    for (int j = 0; j < 8; j++) bv[j] = Bias[colbase + j];
    #pragma unroll
    for (int i = 0; i < 8; i++) {
        int m  = m0 + ty*8 + i;
        int bb = m / NTOK;
        int nn = m - bb*NTOK;
        #pragma unroll
        for (int j = 0; j < 8; j++) {
            int jcol = colbase + j;
            int t3  = jcol >> 8;
            int rem = jcol & 255;
            int hh  = rem >> 5;
            int dd  = rem & 31;
            float v = c[i][j] + bv[j];
            if (t3 == 0)
                g_q [(((size_t)bb*HEADS + hh)*NTOK + nn)*HD + dd] = v * SCALE;
            else if (t3 == 1)
                g_kT[(((size_t)bb*HEADS + hh)*HD + dd)*NTOK + nn] = v;
            else
                g_vT[(((size_t)bb*HEADS + hh)*HD + dd)*NTOK + nn] = v;
        }
    }
}

__global__ __launch_bounds__(256)
void proj_gemm(const float* __restrict__ W,
               const float* __restrict__ Bias,
               float* __restrict__ Out)
{
    __shared__ float Ast[BKK][BM];
    __shared__ float Bs [BKK][BN];
    const int ldb = DIM;             // 256
    int tid = threadIdx.x;
    int tx = tid & 15, ty = tid >> 4;
    int m0 = blockIdx.x * BM, n0 = blockIdx.y * BN;
    float c[8][8] = {};

    for (int k0 = 0; k0 < DIM; k0 += BKK) {
        #pragma unroll
        for (int u = 0; u < 2; u++) {
            int f = tid*2 + u;
            int ar = f >> 2, ac = (f & 3) * 4;
            float4 av = *(const float4*)(g_ao + (size_t)(m0 + ar)*DIM + k0 + ac);
            Ast[ac+0][ar] = av.x; Ast[ac+1][ar] = av.y;
            Ast[ac+2][ar] = av.z; Ast[ac+3][ar] = av.w;
            int br = f >> 5, bc = (f & 31) * 4;
            *(float4*)(&Bs[br][bc]) =
                *(const float4*)(W + (size_t)(k0 + br)*ldb + n0 + bc);
        }
        __syncthreads();
        #pragma unroll
        for (int k = 0; k < BKK; k++) {
            float4 a0 = *(float4*)(&Ast[k][ty*8]);
            float4 a1 = *(float4*)(&Ast[k][ty*8+4]);
            float4 b0 = *(float4*)(&Bs [k][tx*8]);
            float4 b1 = *(float4*)(&Bs [k][tx*8+4]);
            float a[8] = {a0.x,a0.y,a0.z,a0.w,a1.x,a1.y,a1.z,a1.w};
            float b[8] = {b0.x,b0.y,b0.z,b0.w,b1.x,b1.y,b1.z,b1.w};
            #pragma unroll
            for (int i = 0; i < 8; i++)
                #pragma unroll
                for (int j = 0; j < 8; j++)
                    c[i][j] += a[i]*b[j];
        }
        __syncthreads();
    }

    int colbase = n0 + tx*8;
    float bv[8];
    #pragma unroll
    for (int j = 0; j < 8; j++) bv[j] = Bias[colbase + j];
    #pragma unroll
    for (int i = 0; i < 8; i++) {
        int m = m0 + ty*8 + i;
        #pragma unroll
        for (int j = 0; j < 8; j++)
            Out[(size_t)m*DIM + colbase + j] = c[i][j] + bv[j];
    }
}

// ============================================================================
// Kernel 2: attention. One block per (window, head). 256 threads, 8 warps.
// Each warp processes 4 query rows at a time (register row-blocking).
// ============================================================================
__global__ __launch_bounds__(256)
void attn_kernel()
{
    extern __shared__ float sm[];
    float* ksT  = sm;                       // [32][KSTRIDE]
    float* vsT  = sm + 32*KSTRIDE;          // [32][KSTRIDE]
    float* pbuf = sm + 64*KSTRIDE;          // [8 warps][4 rows][PSTRIDE]

    int tid = threadIdx.x, lane = tid & 31, warp = tid >> 5;
    int bh = blockIdx.x;
    int b = bh >> 3, h = bh & 7;
    int w = b & (NWIN-1);

    const float* kg = g_kT + (size_t)bh*HD*NTOK;
    const float* vg = g_vT + (size_t)bh*HD*NTOK;
    for (int idx = tid; idx < 32*KSTRIDE; idx += 256) {
        int d = idx / KSTRIDE, j = idx - d*KSTRIDE;
        float kv = 0.f, vv = 0.f;
        if (j < NTOK) { kv = kg[d*NTOK + j]; vv = vg[d*NTOK + j]; }
        ksT[idx] = kv; vsT[idx] = vv;
    }
    __syncthreads();

    const float* bmh = g_bm + (size_t)(w*HEADS + h)*NTOK*PSTRIDE;
    const float* qg  = g_q  + (size_t)bh*NTOK*HD;
    float* pw = pbuf + warp*4*PSTRIDE;

    for (int g = warp; g*4 < NTOK; g += 8) {
        int i0 = g*4;
        int nrows = min(4, NTOK - i0);

        float qd[4];
        #pragma unroll
        for (int r = 0; r < 4; r++)
            qd[r] = (r < nrows) ? qg[(i0+r)*HD + lane] : 0.f;

        float rowmax[4] = {-1e30f,-1e30f,-1e30f,-1e30f};

        // ------ pass 1: scores = bias+mask + q.kT, track max, store to p ------
        #pragma unroll
        for (int t = 0; t < 3; t++) {
            int j0 = t*128 + lane*4;
            bool vlane = (j0 < PSTRIDE);
            int js = vlane ? j0 : 0;

            float4 s[4];
            #pragma unroll
            for (int r = 0; r < 4; r++) {
                if (r < nrows) s[r] = *(const float4*)(bmh + (size_t)(i0+r)*PSTRIDE + js);
                else           s[r] = make_float4(0.f,0.f,0.f,0.f);
            }
            #pragma unroll
            for (int d = 0; d < 32; d++) {
                float4 kk = *(const float4*)(ksT + d*KSTRIDE + js);
                #pragma unroll
                for (int r = 0; r < 4; r++) {
                    float qv = __shfl_sync(0xffffffffu, qd[r], d);
                    s[r].x += qv*kk.x; s[r].y += qv*kk.y;
                    s[r].z += qv*kk.z; s[r].w += qv*kk.w;
                }
            }
            // kill out-of-range columns
            #pragma unroll
            for (int r = 0; r < 4; r++) {
                if (j0+0 >= NTOK) s[r].x = -1e30f;
                if (j0+1 >= NTOK) s[r].y = -1e30f;
                if (j0+2 >= NTOK) s[r].z = -1e30f;
                if (j0+3 >= NTOK) s[r].w = -1e30f;
            }
            if (vlane) {
                #pragma unroll
                for (int r = 0; r < 4; r++) {
                    if (r < nrows) {
                        rowmax[r] = fmaxf(rowmax[r],
                                     fmaxf(fmaxf(s[r].x,s[r].y), fmaxf(s[r].z,s[r].w)));
                        *(float4*)(pw + r*PSTRIDE + j0) = s[r];
                    }
                }
            }
        }
        #pragma unroll
        for (int r = 0; r < 4; r++) {
            float m = rowmax[r];
            #pragma unroll
            for (int o = 16; o; o >>= 1) m = fmaxf(m, __shfl_xor_sync(0xffffffffu, m, o));
            rowmax[r] = m;
        }
        __syncwarp();

        // ------ pass 2: exp + sum ------
        float rsum[4] = {0.f,0.f,0.f,0.f};
        #pragma unroll
        for (int t = 0; t < 3; t++) {
            int j0 = t*128 + lane*4;
            if (j0 < PSTRIDE) {
                #pragma unroll
                for (int r = 0; r < 4; r++) {
                    if (r < nrows) {
                        float4 pv = *(float4*)(pw + r*PSTRIDE + j0);
                        pv.x = __expf(pv.x - rowmax[r]);
                        pv.y = __expf(pv.y - rowmax[r]);
                        pv.z = __expf(pv.z - rowmax[r]);
                        pv.w = __expf(pv.w - rowmax[r]);
                        rsum[r] += pv.x + pv.y + pv.z + pv.w;
                        *(float4*)(pw + r*PSTRIDE + j0) = pv;
                    }
                }
            }
        }
        #pragma unroll
        for (int r = 0; r < 4; r++) {
            float sv = rsum[r];
            #pragma unroll
            for (int o = 16; o; o >>= 1) sv += __shfl_xor_sync(0xffffffffu, sv, o);
            rsum[r] = sv;
        }
        __syncwarp();

        // ------ pass 3: out[d=lane] = sum_j p[j] * vT[d][j] ------
        float4 acc[4];
        #pragma unroll
        for (int r = 0; r < 4; r++) acc[r] = make_float4(0.f,0.f,0.f,0.f);
        const float* vrow = vsT + lane*KSTRIDE;
        for (int jt = 0; jt < PSTRIDE; jt += 4) {
            float4 vv = *(const float4*)(vrow + jt);
            #pragma unroll
            for (int r = 0; r < 4; r++) {
                float4 pp = *(const float4*)(pw + r*PSTRIDE + jt);
                acc[r].x += pp.x*vv.x; acc[r].y += pp.y*vv.y;
                acc[r].z += pp.z*vv.z; acc[r].w += pp.w*vv.w;
            }
        }
        #pragma unroll
        for (int r = 0; r < 4; r++) {
            if (r < nrows) {
                float o = (acc[r].x + acc[r].y + acc[r].z + acc[r].w) / rsum[r];
                g_ao[((size_t)b*NTOK + i0 + r)*DIM + h*HD + lane] = o;
            }
        }
        __syncwarp();   // p-buffer reused by this warp next group
    }
}

// ============================================================================
// launch
// ============================================================================
extern "C" void kernel_launch(void* const* d_in, const int* in_sizes, int n_in,
                              void* d_out, int out_size)
{
    const float* x      = (const float*)d_in[0];
    const float* mask   = (const float*)d_in[1];
    const float* qkv_w  = (const float*)d_in[2];
    const float* qkv_b  = (const float*)d_in[3];
    const float* proj_w = (const float*)d_in[4];
    const float* proj_b = (const float*)d_in[5];
    const float* rpb    = (const float*)d_in[6];
    const int*   rel    = (const int*)d_in[7];
    float* out = (float*)d_out;

    (void)in_sizes; (void)n_in; (void)out_size;

    const int attn_smem = (64*KSTRIDE + 8*4*PSTRIDE) * (int)sizeof(float); // 135168
    cudaFuncSetAttribute(attn_kernel, cudaFuncAttributeMaxDynamicSharedMemorySize, attn_smem);

    bias_prep<<<dim3(NTOK, NWIN*HEADS), 128>>>(mask, rpb, rel);
    qkv_gemm <<<dim3(MROWS/BM, (3*DIM)/BN), 256>>>(x, qkv_w, qkv_b);
    attn_kernel<<<BATCH*HEADS, 256, attn_smem>>>();
    proj_gemm<<<dim3(MROWS/BM, DIM/BN), 256>>>(proj_w, proj_b, out);
}

// round 6
// speedup vs baseline: 1.0195x; 1.0195x over previous
#include <cuda_runtime.h>
#include <cuda_bf16.h>

// ---------------- problem constants ----------------
#define BATCH   256
#define NTOK    343
#define DIM     256
#define HEADS   8
#define HD      32
#define NWIN    64
#define SCALE   0.17677669529663687f

#define MROWS   (BATCH*NTOK)           // 87808
#define KSTRIDE 356                    // == 4 (mod 32): conflict-free strided LDS.128
#define PSTRIDE 344
#define RPW     8                      // rows per warp in attention

// ---------------- packed f32x2 helpers (sm_103a FFMA2) ----------------
typedef unsigned long long u64t;

__device__ __forceinline__ u64t f2pack(float x, float y) {
    u64t r; asm("mov.b64 %0, {%1,%2};" : "=l"(r) : "f"(x), "f"(y)); return r;
}
__device__ __forceinline__ void f2unpack(u64t p, float& x, float& y) {
    asm("mov.b64 {%0,%1}, %2;" : "=f"(x), "=f"(y) : "l"(p));
}
__device__ __forceinline__ void ffma2(u64t& d, u64t a, u64t b) {
    asm("fma.rn.f32x2 %0, %1, %2, %0;" : "+l"(d) : "l"(a), "l"(b));
}

// ---------------- scratch ----------------
__device__ float g_q [BATCH*HEADS*NTOK*HD];
__device__ float g_kT[BATCH*HEADS*HD*NTOK];
__device__ float g_vT[BATCH*HEADS*HD*NTOK];
__device__ float g_ao[MROWS*DIM];
__device__ float g_bm[(size_t)NWIN*HEADS*NTOK*PSTRIDE];

// ============================================================================
// Kernel 0: fused bias+mask
// ============================================================================
__global__ void bias_prep(const float* __restrict__ mask,
                          const float* __restrict__ table,
                          const int*   __restrict__ rel)
{
    int i  = blockIdx.x;
    int wh = blockIdx.y;
    int w = wh >> 3, h = wh & 7;
    const float* mrow = mask + ((size_t)w*NTOK + i)*NTOK;
    const int*   rrow = rel  + i*NTOK;
    float*       orow = g_bm + ((size_t)wh*NTOK + i)*PSTRIDE;
    for (int j = threadIdx.x; j < PSTRIDE; j += blockDim.x) {
        float v = 0.f;
        if (j < NTOK) v = mrow[j] + table[rrow[j]*HEADS + h];
        orow[j] = v;
    }
}

// ============================================================================
// Tiled fp32 GEMMs with packed FFMA2 inner loop.
// BM=BN=128, BK=16, 256 threads, 8x8 per thread (as 8 x 4-pair).
// ============================================================================
#define BM 128
#define BN 128
#define BKK 16

__global__ __launch_bounds__(256)
void qkv_gemm(const float* __restrict__ X,
              const float* __restrict__ W,
              const float* __restrict__ Bias)
{
    __shared__ float Ast[BKK][BM];
    __shared__ float Bs [BKK][BN];
    const int ldb = 3*DIM;
    int tid = threadIdx.x;
    int tx = tid & 15, ty = tid >> 4;
    int m0 = blockIdx.x * BM, n0 = blockIdx.y * BN;
    u64t c2[8][4] = {};

    for (int k0 = 0; k0 < DIM; k0 += BKK) {
        #pragma unroll
        for (int u = 0; u < 2; u++) {
            int f = tid*2 + u;
            int ar = f >> 2, ac = (f & 3) * 4;
            float4 av = *(const float4*)(X + (size_t)(m0 + ar)*DIM + k0 + ac);
            Ast[ac+0][ar] = av.x; Ast[ac+1][ar] = av.y;
            Ast[ac+2][ar] = av.z; Ast[ac+3][ar] = av.w;
            int br = f >> 5, bc = (f & 31) * 4;
            *(float4*)(&Bs[br][bc]) =
                *(const float4*)(W + (size_t)(k0 + br)*ldb + n0 + bc);
        }
        __syncthreads();
        #pragma unroll
        for (int k = 0; k < BKK; k++) {
            float4 a0 = *(float4*)(&Ast[k][ty*8]);
            float4 a1 = *(float4*)(&Ast[k][ty*8+4]);
            ulonglong2 b01 = *(ulonglong2*)(&Bs[k][tx*8]);
            ulonglong2 b23 = *(ulonglong2*)(&Bs[k][tx*8+4]);
            u64t bp[4] = {b01.x, b01.y, b23.x, b23.y};
            float a8[8] = {a0.x,a0.y,a0.z,a0.w,a1.x,a1.y,a1.z,a1.w};
            #pragma unroll
            for (int i = 0; i < 8; i++) {
                u64t aa = f2pack(a8[i], a8[i]);
                #pragma unroll
                for (int j = 0; j < 4; j++) ffma2(c2[i][j], aa, bp[j]);
            }
        }
        __syncthreads();
    }

    int colbase = n0 + tx*8;
    float bv[8];
    #pragma unroll
    for (int j = 0; j < 8; j++) bv[j] = Bias[colbase + j];
    #pragma unroll
    for (int i = 0; i < 8; i++) {
        int m  = m0 + ty*8 + i;
        int bb = m / NTOK;
        int nn = m - bb*NTOK;
        float cf[8];
        #pragma unroll
        for (int j = 0; j < 4; j++) f2unpack(c2[i][j], cf[2*j], cf[2*j+1]);
        #pragma unroll
        for (int j = 0; j < 8; j++) {
            int jcol = colbase + j;
            int t3  = jcol >> 8;
            int rem = jcol & 255;
            int hh  = rem >> 5;
            int dd  = rem & 31;
            float v = cf[j] + bv[j];
            if (t3 == 0)
                g_q [(((size_t)bb*HEADS + hh)*NTOK + nn)*HD + dd] = v * SCALE;
            else if (t3 == 1)
                g_kT[(((size_t)bb*HEADS + hh)*HD + dd)*NTOK + nn] = v;
            else
                g_vT[(((size_t)bb*HEADS + hh)*HD + dd)*NTOK + nn] = v;
        }
    }
}

__global__ __launch_bounds__(256)
void proj_gemm(const float* __restrict__ W,
               const float* __restrict__ Bias,
               float* __restrict__ Out)
{
    __shared__ float Ast[BKK][BM];
    __shared__ float Bs [BKK][BN];
    const int ldb = DIM;
    int tid = threadIdx.x;
    int tx = tid & 15, ty = tid >> 4;
    int m0 = blockIdx.x * BM, n0 = blockIdx.y * BN;
    u64t c2[8][4] = {};

    for (int k0 = 0; k0 < DIM; k0 += BKK) {
        #pragma unroll
        for (int u = 0; u < 2; u++) {
            int f = tid*2 + u;
            int ar = f >> 2, ac = (f & 3) * 4;
            float4 av = *(const float4*)(g_ao + (size_t)(m0 + ar)*DIM + k0 + ac);
            Ast[ac+0][ar] = av.x; Ast[ac+1][ar] = av.y;
            Ast[ac+2][ar] = av.z; Ast[ac+3][ar] = av.w;
            int br = f >> 5, bc = (f & 31) * 4;
            *(float4*)(&Bs[br][bc]) =
                *(const float4*)(W + (size_t)(k0 + br)*ldb + n0 + bc);
        }
        __syncthreads();
        #pragma unroll
        for (int k = 0; k < BKK; k++) {
            float4 a0 = *(float4*)(&Ast[k][ty*8]);
            float4 a1 = *(float4*)(&Ast[k][ty*8+4]);
            ulonglong2 b01 = *(ulonglong2*)(&Bs[k][tx*8]);
            ulonglong2 b23 = *(ulonglong2*)(&Bs[k][tx*8+4]);
            u64t bp[4] = {b01.x, b01.y, b23.x, b23.y};
            float a8[8] = {a0.x,a0.y,a0.z,a0.w,a1.x,a1.y,a1.z,a1.w};
            #pragma unroll
            for (int i = 0; i < 8; i++) {
                u64t aa = f2pack(a8[i], a8[i]);
                #pragma unroll
                for (int j = 0; j < 4; j++) ffma2(c2[i][j], aa, bp[j]);
            }
        }
        __syncthreads();
    }

    int colbase = n0 + tx*8;
    float bv[8];
    #pragma unroll
    for (int j = 0; j < 8; j++) bv[j] = Bias[colbase + j];
    #pragma unroll
    for (int i = 0; i < 8; i++) {
        int m = m0 + ty*8 + i;
        float cf[8];
        #pragma unroll
        for (int j = 0; j < 4; j++) f2unpack(c2[i][j], cf[2*j], cf[2*j+1]);
        #pragma unroll
        for (int j = 0; j < 8; j++)
            Out[(size_t)m*DIM + colbase + j] = cf[j] + bv[j];
    }
}

// ============================================================================
// Kernel 2: attention. 1 block / (window,head). 8 warps x 8 rows each.
// Packed FFMA2; q pre-duplicated (q,q) in smem -> broadcast LDS, no shfl.
// ============================================================================
__global__ __launch_bounds__(256)
void attn_kernel()
{
    extern __shared__ float sm[];
    float* ksT  = sm;                                 // [32][KSTRIDE]
    float* vsT  = sm + 32*KSTRIDE;                    // [32][KSTRIDE]
    float* pbuf = sm + 64*KSTRIDE;                    // [8][RPW][PSTRIDE]
    u64t*  qs   = (u64t*)(sm + 64*KSTRIDE + 8*RPW*PSTRIDE); // [8][RPW][32]

    int tid = threadIdx.x, lane = tid & 31, warp = tid >> 5;
    int bh = blockIdx.x;
    int b = bh >> 3, h = bh & 7;
    int w = b & (NWIN-1);

    const float* kg = g_kT + (size_t)bh*HD*NTOK;
    const float* vg = g_vT + (size_t)bh*HD*NTOK;
    for (int idx = tid; idx < 32*KSTRIDE; idx += 256) {
        int d = idx / KSTRIDE, j = idx - d*KSTRIDE;
        float kv = 0.f, vv = 0.f;
        if (j < NTOK) { kv = kg[d*NTOK + j]; vv = vg[d*NTOK + j]; }
        ksT[idx] = kv; vsT[idx] = vv;
    }
    __syncthreads();

    const float* bmh = g_bm + (size_t)(w*HEADS + h)*NTOK*PSTRIDE;
    const float* qg  = g_q  + (size_t)bh*NTOK*HD;
    float* pw   = pbuf + warp*RPW*PSTRIDE;
    u64t*  qs_w = qs   + warp*RPW*32;

    for (int g = warp; g*RPW < NTOK; g += 8) {
        int i0 = g*RPW;
        int nrows = min(RPW, NTOK - i0);

        // stage duplicated q packs: qs_w[r][d] = (q,q)
        #pragma unroll
        for (int r = 0; r < RPW; r++) {
            float qv = (r < nrows) ? qg[(i0+r)*HD + lane] : 0.f;
            qs_w[r*32 + lane] = f2pack(qv, qv);
        }
        __syncwarp();

        float rowmax[RPW];
        #pragma unroll
        for (int r = 0; r < RPW; r++) rowmax[r] = -1e30f;

        // ---- pass 1: scores = bias+mask + q.kT ----
        #pragma unroll
        for (int t = 0; t < 3; t++) {
            int j0 = t*128 + lane*4;
            bool vlane = (j0 < PSTRIDE);
            int js = vlane ? j0 : 0;

            u64t s2[RPW][2];
            #pragma unroll
            for (int r = 0; r < RPW; r++) {
                if (r < nrows) {
                    ulonglong2 bb = *(const ulonglong2*)(bmh + (size_t)(i0+r)*PSTRIDE + js);
                    s2[r][0] = bb.x; s2[r][1] = bb.y;
                } else { s2[r][0] = 0ULL; s2[r][1] = 0ULL; }
            }
            #pragma unroll 4
            for (int d = 0; d < 32; d += 2) {
                ulonglong2 k0 = *(const ulonglong2*)(ksT + d*KSTRIDE + js);
                ulonglong2 k1 = *(const ulonglong2*)(ksT + (d+1)*KSTRIDE + js);
                #pragma unroll
                for (int r = 0; r < RPW; r++) {
                    ulonglong2 qq = *(const ulonglong2*)(qs_w + r*32 + d);
                    ffma2(s2[r][0], qq.x, k0.x); ffma2(s2[r][1], qq.x, k0.y);
                    ffma2(s2[r][0], qq.y, k1.x); ffma2(s2[r][1], qq.y, k1.y);
                }
            }
            #pragma unroll
            for (int r = 0; r < RPW; r++) {
                if (r < nrows && vlane) {
                    float s0,s1,sa,sb;
                    f2unpack(s2[r][0], s0, s1);
                    f2unpack(s2[r][1], sa, sb);
                    if (j0+0 >= NTOK) s0 = -1e30f;
                    if (j0+1 >= NTOK) s1 = -1e30f;
                    if (j0+2 >= NTOK) sa = -1e30f;
                    if (j0+3 >= NTOK) sb = -1e30f;
                    rowmax[r] = fmaxf(rowmax[r], fmaxf(fmaxf(s0,s1), fmaxf(sa,sb)));
                    *(float4*)(pw + r*PSTRIDE + j0) = make_float4(s0,s1,sa,sb);
                }
            }
        }
        #pragma unroll
        for (int r = 0; r < RPW; r++) {
            float m = rowmax[r];
            #pragma unroll
            for (int o = 16; o; o >>= 1) m = fmaxf(m, __shfl_xor_sync(0xffffffffu, m, o));
            rowmax[r] = m;
        }
        __syncwarp();

        // ---- pass 2: exp + rowsum ----
        float rsum[RPW];
        #pragma unroll
        for (int r = 0; r < RPW; r++) rsum[r] = 0.f;
        #pragma unroll
        for (int t = 0; t < 3; t++) {
            int j0 = t*128 + lane*4;
            if (j0 < PSTRIDE) {
                #pragma unroll
                for (int r = 0; r < RPW; r++) {
                    if (r < nrows) {
                        float4 pv = *(float4*)(pw + r*PSTRIDE + j0);
                        pv.x = __expf(pv.x - rowmax[r]);
                        pv.y = __expf(pv.y - rowmax[r]);
                        pv.z = __expf(pv.z - rowmax[r]);
                        pv.w = __expf(pv.w - rowmax[r]);
                        rsum[r] += pv.x + pv.y + pv.z + pv.w;
                        *(float4*)(pw + r*PSTRIDE + j0) = pv;
                    }
                }
            }
        }
        #pragma unroll
        for (int r = 0; r < RPW; r++) {
            float sv = rsum[r];
            #pragma unroll
            for (int o = 16; o; o >>= 1) sv += __shfl_xor_sync(0xffffffffu, sv, o);
            rsum[r] = sv;
        }
        __syncwarp();

        // ---- pass 3: out[d=lane] = sum_j p[j] * vT[d][j] ----
        u64t acc2[RPW][2];
        #pragma unroll
        for (int r = 0; r < RPW; r++) { acc2[r][0] = 0ULL; acc2[r][1] = 0ULL; }
        const float* vrow = vsT + lane*KSTRIDE;
        for (int jt = 0; jt < PSTRIDE; jt += 4) {
            ulonglong2 vv = *(const ulonglong2*)(vrow + jt);
            #pragma unroll
            for (int r = 0; r < RPW; r++) {
                ulonglong2 pp = *(const ulonglong2*)(pw + r*PSTRIDE + jt);
                ffma2(acc2[r][0], pp.x, vv.x);
                ffma2(acc2[r][1], pp.y, vv.y);
            }
        }
        #pragma unroll
        for (int r = 0; r < RPW; r++) {
            if (r < nrows) {
                float x0,x1,x2f,x3;
                f2unpack(acc2[r][0], x0, x1);
                f2unpack(acc2[r][1], x2f, x3);
                float o = (x0 + x1 + x2f + x3) / rsum[r];
                g_ao[((size_t)b*NTOK + i0 + r)*DIM + h*HD + lane] = o;
            }
        }
        __syncwarp();
    }
}

// ============================================================================
// launch
// ============================================================================
extern "C" void kernel_launch(void* const* d_in, const int* in_sizes, int n_in,
                              void* d_out, int out_size)
{
    const float* x      = (const float*)d_in[0];
    const float* mask   = (const float*)d_in[1];
    const float* qkv_w  = (const float*)d_in[2];
    const float* qkv_b  = (const float*)d_in[3];
    const float* proj_w = (const float*)d_in[4];
    const float* proj_b = (const float*)d_in[5];
    const float* rpb    = (const float*)d_in[6];
    const int*   rel    = (const int*)d_in[7];
    float* out = (float*)d_out;

    (void)in_sizes; (void)n_in; (void)out_size;

    const int attn_smem = (64*KSTRIDE + 8*RPW*PSTRIDE + 8*RPW*32*2) * (int)sizeof(float); // 195584
    cudaFuncSetAttribute(attn_kernel, cudaFuncAttributeMaxDynamicSharedMemorySize, attn_smem);

    bias_prep<<<dim3(NTOK, NWIN*HEADS), 128>>>(mask, rpb, rel);
    qkv_gemm <<<dim3(MROWS/BM, (3*DIM)/BN), 256>>>(x, qkv_w, qkv_b);
    attn_kernel<<<BATCH*HEADS, 256, attn_smem>>>();
    proj_gemm<<<dim3(MROWS/BM, DIM/BN), 256>>>(proj_w, proj_b, out);
}

// round 15
// speedup vs baseline: 1.1609x; 1.1387x over previous
#include <cuda_runtime.h>
#include <cuda_bf16.h>

// ---------------- problem constants ----------------
#define BATCH   256
#define NTOK    343
#define DIM     256
#define HEADS   8
#define HD      32
#define NWIN    64
#define SCALE   0.17677669529663687f

#define MROWS   (BATCH*NTOK)           // 87808
#define KSTRIDE 356
#define PSTRIDE 344
#define RPW     8

#define ASTRIDE 40                     // smem row stride in bf16 (80B = 20 banks -> conflict-free)

typedef unsigned long long u64t;
typedef unsigned int u32t;

__device__ __forceinline__ u64t f2pack(float x, float y) {
    u64t r; asm("mov.b64 %0, {%1,%2};" : "=l"(r) : "f"(x), "f"(y)); return r;
}
__device__ __forceinline__ void f2unpack(u64t p, float& x, float& y) {
    asm("mov.b64 {%0,%1}, %2;" : "=f"(x), "=f"(y) : "l"(p));
}
__device__ __forceinline__ void ffma2(u64t& d, u64t a, u64t b) {
    asm("fma.rn.f32x2 %0, %1, %2, %0;" : "+l"(d) : "l"(a), "l"(b));
}

__device__ __forceinline__ void mma16816(float* c,
        u32t a0, u32t a1, u32t a2, u32t a3, u32t b0, u32t b1)
{
    asm volatile(
        "mma.sync.aligned.m16n8k16.row.col.f32.bf16.bf16.f32 "
        "{%0,%1,%2,%3}, {%4,%5,%6,%7}, {%8,%9}, {%0,%1,%2,%3};"
        : "+f"(c[0]), "+f"(c[1]), "+f"(c[2]), "+f"(c[3])
        : "r"(a0), "r"(a1), "r"(a2), "r"(a3), "r"(b0), "r"(b1));
}

// ---------------- scratch ----------------
__device__ __align__(16) float g_q [BATCH*HEADS*NTOK*HD];
__device__ __align__(16) float g_kT[BATCH*HEADS*HD*NTOK];
__device__ __align__(16) float g_vT[BATCH*HEADS*HD*NTOK];
__device__ __align__(16) float g_bm[(size_t)NWIN*HEADS*NTOK*PSTRIDE];

__device__ __align__(16) __nv_bfloat16 g_xh [MROWS*DIM];     // x split hi/lo, [m][k]
__device__ __align__(16) __nv_bfloat16 g_xl [MROWS*DIM];
__device__ __align__(16) __nv_bfloat16 g_aoh[MROWS*DIM];     // attn out split, [m][k]
__device__ __align__(16) __nv_bfloat16 g_aol[MROWS*DIM];
__device__ __align__(16) __nv_bfloat16 g_wqh[3*DIM*DIM];     // qkv_w^T split, [n][k]
__device__ __align__(16) __nv_bfloat16 g_wql[3*DIM*DIM];
__device__ __align__(16) __nv_bfloat16 g_wph[DIM*DIM];       // proj_w^T split, [n][k]
__device__ __align__(16) __nv_bfloat16 g_wpl[DIM*DIM];

// ============================================================================
// split kernels — destinations are referenced as device symbols INSIDE device
// code (passing __device__ symbols as host-side kernel args is invalid and was
// the R8/R10 bug: splits wrote nowhere, zero-init globals -> zero output).
// ============================================================================
__global__ __launch_bounds__(256)
void split_x_kernel(const float* __restrict__ X, int n4)
{
    int i = blockIdx.x*blockDim.x + threadIdx.x;
    if (i >= n4) return;
    float4 v = ((const float4*)X)[i];
    __nv_bfloat16 h0 = __float2bfloat16(v.x);
    __nv_bfloat16 h1 = __float2bfloat16(v.y);
    __nv_bfloat16 h2 = __float2bfloat16(v.z);
    __nv_bfloat16 h3 = __float2bfloat16(v.w);
    __nv_bfloat16 l0 = __float2bfloat16(v.x - __bfloat162float(h0));
    __nv_bfloat16 l1 = __float2bfloat16(v.y - __bfloat162float(h1));
    __nv_bfloat16 l2 = __float2bfloat16(v.z - __bfloat162float(h2));
    __nv_bfloat16 l3 = __float2bfloat16(v.w - __bfloat162float(h3));
    __nv_bfloat162* H2 = (__nv_bfloat162*)g_xh;
    __nv_bfloat162* L2 = (__nv_bfloat162*)g_xl;
    H2[2*i]   = __halves2bfloat162(h0, h1);
    H2[2*i+1] = __halves2bfloat162(h2, h3);
    L2[2*i]   = __halves2bfloat162(l0, l1);
    L2[2*i+1] = __halves2bfloat162(l2, l3);
}

// qkv_w [K=256][N=768] row-major -> g_wqh/g_wql [N][K]
__global__ __launch_bounds__(256)
void split_wq_kernel(const float* __restrict__ W)
{
    int idx = blockIdx.x*blockDim.x + threadIdx.x;
    if (idx >= DIM*3*DIM) return;
    float v = W[idx];
    int k = idx / (3*DIM), n = idx - k*(3*DIM);
    __nv_bfloat16 h = __float2bfloat16(v);
    __nv_bfloat16 l = __float2bfloat16(v - __bfloat162float(h));
    g_wqh[(size_t)n*DIM + k] = h;
    g_wql[(size_t)n*DIM + k] = l;
}

// proj_w [K=256][N=256] row-major -> g_wph/g_wpl [N][K]
__global__ __launch_bounds__(256)
void split_wp_kernel(const float* __restrict__ W)
{
    int idx = blockIdx.x*blockDim.x + threadIdx.x;
    if (idx >= DIM*DIM) return;
    float v = W[idx];
    int k = idx / DIM, n = idx - k*DIM;
    __nv_bfloat16 h = __float2bfloat16(v);
    __nv_bfloat16 l = __float2bfloat16(v - __bfloat162float(h));
    g_wph[(size_t)n*DIM + k] = h;
    g_wpl[(size_t)n*DIM + k] = l;
}

// ============================================================================
// bias+mask prep
// ============================================================================
__global__ __launch_bounds__(128)
void bias_prep(const float* __restrict__ mask,
               const float* __restrict__ table,
               const int*   __restrict__ rel)
{
    int i  = blockIdx.x;
    int wh = blockIdx.y;
    int w = wh >> 3, h = wh & 7;
    const float* mrow = mask + ((size_t)w*NTOK + i)*NTOK;
    const int*   rrow = rel  + i*NTOK;
    float*       orow = g_bm + ((size_t)wh*NTOK + i)*PSTRIDE;
    for (int j = threadIdx.x; j < PSTRIDE; j += blockDim.x) {
        float v = 0.f;
        if (j < NTOK) v = mrow[j] + table[rrow[j]*HEADS + h];
        orow[j] = v;
    }
}

// ============================================================================
// split-bf16 tensor-core GEMM core: C[128x128] = A[128x256] * B^T
// D += Ah*Bh + Ah*Bl + Al*Bh  (drops Al*Bl ~ 2^-18)
// Called from device code; symbol-valued pointers are valid there.
// ============================================================================
__device__ __forceinline__ void gemm_bf16_core(
    const __nv_bfloat16* __restrict__ Ah, const __nv_bfloat16* __restrict__ Al,
    const __nv_bfloat16* __restrict__ Bh, const __nv_bfloat16* __restrict__ Bl,
    int m0, int n0, int tid, float cfr[2][8][4],
    __nv_bfloat16* sAh, __nv_bfloat16* sAl,
    __nv_bfloat16* sBh, __nv_bfloat16* sBl)
{
    int lane = tid & 31, warp = tid >> 5;
    int wm = warp >> 1, wn = warp & 1;
    int g = lane >> 2, tig = lane & 3;

    for (int k0 = 0; k0 < DIM; k0 += 32) {
        // cooperative load: 4 arrays x 128 rows x 32 bf16 = 2048 uint4
        #pragma unroll
        for (int i = 0; i < 8; i++) {
            int idx = tid + i*256;
            int row = idx & 127;
            int rest = idx >> 7;             // 0..15
            int arr = rest & 3, chunk = rest >> 2;
            const __nv_bfloat16* src;
            __nv_bfloat16* dst;
            if (arr == 0)      { src = Ah + (size_t)(m0+row)*DIM; dst = sAh; }
            else if (arr == 1) { src = Al + (size_t)(m0+row)*DIM; dst = sAl; }
            else if (arr == 2) { src = Bh + (size_t)(n0+row)*DIM; dst = sBh; }
            else               { src = Bl + (size_t)(n0+row)*DIM; dst = sBl; }
            *(uint4*)(dst + row*ASTRIDE + chunk*8) = *(const uint4*)(src + k0 + chunk*8);
        }
        __syncthreads();

        #pragma unroll
        for (int kk = 0; kk < 32; kk += 16) {
            u32t ah[2][4], al[2][4];
            #pragma unroll
            for (int mt = 0; mt < 2; mt++) {
                int mbase = wm*32 + mt*16 + g;
                const __nv_bfloat16* ph = sAh + mbase*ASTRIDE + kk + tig*2;
                const __nv_bfloat16* pl = sAl + mbase*ASTRIDE + kk + tig*2;
                ah[mt][0] = *(const u32t*)(ph);
                ah[mt][1] = *(const u32t*)(ph + 8*ASTRIDE);
                ah[mt][2] = *(const u32t*)(ph + 8);
                ah[mt][3] = *(const u32t*)(ph + 8*ASTRIDE + 8);
                al[mt][0] = *(const u32t*)(pl);
                al[mt][1] = *(const u32t*)(pl + 8*ASTRIDE);
                al[mt][2] = *(const u32t*)(pl + 8);
                al[mt][3] = *(const u32t*)(pl + 8*ASTRIDE + 8);
            }
            #pragma unroll
            for (int nt = 0; nt < 8; nt++) {
                int nbase = wn*64 + nt*8 + g;
                const __nv_bfloat16* qh = sBh + nbase*ASTRIDE + kk + tig*2;
                const __nv_bfloat16* ql = sBl + nbase*ASTRIDE + kk + tig*2;
                u32t bh0 = *(const u32t*)(qh);
                u32t bh1 = *(const u32t*)(qh + 8);
                u32t bl0 = *(const u32t*)(ql);
                u32t bl1 = *(const u32t*)(ql + 8);
                #pragma unroll
                for (int mt = 0; mt < 2; mt++) {
                    mma16816(cfr[mt][nt], ah[mt][0],ah[mt][1],ah[mt][2],ah[mt][3], bh0, bh1);
                    mma16816(cfr[mt][nt], ah[mt][0],ah[mt][1],ah[mt][2],ah[mt][3], bl0, bl1);
                    mma16816(cfr[mt][nt], al[mt][0],al[mt][1],al[mt][2],al[mt][3], bh0, bh1);
                }
            }
        }
        __syncthreads();
    }
}

// ---------------- qkv GEMM: scatter into q/kT/vT ----------------
__device__ __forceinline__ void qkv_store(int m, int col, float v0, float v1,
                                          const float* __restrict__ Bias)
{
    v0 += Bias[col]; v1 += Bias[col+1];
    int bb = m / NTOK;
    int nn = m - bb*NTOK;
    int t3  = col >> 8;
    int rem = col & 255;
    int hh  = rem >> 5;
    int dd  = rem & 31;
    if (t3 == 0) {
        size_t base = (((size_t)bb*HEADS + hh)*NTOK + nn)*HD + dd;
        g_q[base] = v0 * SCALE; g_q[base+1] = v1 * SCALE;
    } else if (t3 == 1) {
        size_t base = (((size_t)bb*HEADS + hh)*HD + dd)*NTOK + nn;
        g_kT[base] = v0; g_kT[base + NTOK] = v1;
    } else {
        size_t base = (((size_t)bb*HEADS + hh)*HD + dd)*NTOK + nn;
        g_vT[base] = v0; g_vT[base + NTOK] = v1;
    }
}

__global__ __launch_bounds__(256)
void qkv_mma(const float* __restrict__ Bias)
{
    __shared__ __align__(16) __nv_bfloat16 sAh[128*ASTRIDE];
    __shared__ __align__(16) __nv_bfloat16 sAl[128*ASTRIDE];
    __shared__ __align__(16) __nv_bfloat16 sBh[128*ASTRIDE];
    __shared__ __align__(16) __nv_bfloat16 sBl[128*ASTRIDE];
    int tid = threadIdx.x;
    int m0 = blockIdx.x * 128, n0 = blockIdx.y * 128;
    float cfr[2][8][4] = {};

    gemm_bf16_core(g_xh, g_xl, g_wqh, g_wql, m0, n0, tid, cfr, sAh, sAl, sBh, sBl);

    int lane = tid & 31, warp = tid >> 5;
    int wm = warp >> 1, wn = warp & 1;
    int g = lane >> 2, tig = lane & 3;
    #pragma unroll
    for (int mt = 0; mt < 2; mt++) {
        int mr = m0 + wm*32 + mt*16 + g;
        #pragma unroll
        for (int nt = 0; nt < 8; nt++) {
            int col = n0 + wn*64 + nt*8 + tig*2;
            float* cc = cfr[mt][nt];
            qkv_store(mr,     col, cc[0], cc[1], Bias);
            qkv_store(mr + 8, col, cc[2], cc[3], Bias);
        }
    }
}

// ---------------- proj GEMM: writes final output ----------------
__global__ __launch_bounds__(256)
void proj_mma(const float* __restrict__ Bias, float* __restrict__ Out)
{
    __shared__ __align__(16) __nv_bfloat16 sAh[128*ASTRIDE];
    __shared__ __align__(16) __nv_bfloat16 sAl[128*ASTRIDE];
    __shared__ __align__(16) __nv_bfloat16 sBh[128*ASTRIDE];
    __shared__ __align__(16) __nv_bfloat16 sBl[128*ASTRIDE];
    int tid = threadIdx.x;
    int m0 = blockIdx.x * 128, n0 = blockIdx.y * 128;
    float cfr[2][8][4] = {};

    gemm_bf16_core(g_aoh, g_aol, g_wph, g_wpl, m0, n0, tid, cfr, sAh, sAl, sBh, sBl);

    int lane = tid & 31, warp = tid >> 5;
    int wm = warp >> 1, wn = warp & 1;
    int g = lane >> 2, tig = lane & 3;
    #pragma unroll
    for (int mt = 0; mt < 2; mt++) {
        int mr = m0 + wm*32 + mt*16 + g;
        #pragma unroll
        for (int nt = 0; nt < 8; nt++) {
            int col = n0 + wn*64 + nt*8 + tig*2;
            float* cc = cfr[mt][nt];
            float b0 = Bias[col], b1 = Bias[col+1];
            *(float2*)(Out + (size_t)mr*DIM + col)     = make_float2(cc[0]+b0, cc[1]+b1);
            *(float2*)(Out + (size_t)(mr+8)*DIM + col) = make_float2(cc[2]+b0, cc[3]+b1);
        }
    }
}

// ============================================================================
// attention (fp32 FFMA2 path; epilogue emits split-bf16 for proj)
// ============================================================================
__global__ __launch_bounds__(256)
void attn_kernel()
{
    extern __shared__ float sm[];
    float* ksT  = sm;
    float* vsT  = sm + 32*KSTRIDE;
    float* pbuf = sm + 64*KSTRIDE;
    u64t*  qs   = (u64t*)(sm + 64*KSTRIDE + 8*RPW*PSTRIDE);

    int tid = threadIdx.x, lane = tid & 31, warp = tid >> 5;
    int bh = blockIdx.x;
    int b = bh >> 3, h = bh & 7;
    int w = b & (NWIN-1);

    const float* kg = g_kT + (size_t)bh*HD*NTOK;
    const float* vg = g_vT + (size_t)bh*HD*NTOK;
    for (int idx = tid; idx < 32*KSTRIDE; idx += 256) {
        int d = idx / KSTRIDE, j = idx - d*KSTRIDE;
        float kv = 0.f, vv = 0.f;
        if (j < NTOK) { kv = kg[d*NTOK + j]; vv = vg[d*NTOK + j]; }
        ksT[idx] = kv; vsT[idx] = vv;
    }
    __syncthreads();

    const float* bmh = g_bm + (size_t)(w*HEADS + h)*NTOK*PSTRIDE;
    const float* qg  = g_q  + (size_t)bh*NTOK*HD;
    float* pw   = pbuf + warp*RPW*PSTRIDE;
    u64t*  qs_w = qs   + warp*RPW*32;

    for (int g = warp; g*RPW < NTOK; g += 8) {
        int i0 = g*RPW;
        int nrows = min(RPW, NTOK - i0);

        #pragma unroll
        for (int r = 0; r < RPW; r++) {
            float qv = (r < nrows) ? qg[(i0+r)*HD + lane] : 0.f;
            qs_w[r*32 + lane] = f2pack(qv, qv);
        }
        __syncwarp();

        float rowmax[RPW];
        #pragma unroll
        for (int r = 0; r < RPW; r++) rowmax[r] = -1e30f;

        #pragma unroll
        for (int t = 0; t < 3; t++) {
            int j0 = t*128 + lane*4;
            bool vlane = (j0 < PSTRIDE);
            int js = vlane ? j0 : 0;

            u64t s2[RPW][2];
            #pragma unroll
            for (int r = 0; r < RPW; r++) {
                if (r < nrows) {
                    ulonglong2 bb = *(const ulonglong2*)(bmh + (size_t)(i0+r)*PSTRIDE + js);
                    s2[r][0] = bb.x; s2[r][1] = bb.y;
                } else { s2[r][0] = 0ULL; s2[r][1] = 0ULL; }
            }
            #pragma unroll 4
            for (int d = 0; d < 32; d += 2) {
                ulonglong2 k0 = *(const ulonglong2*)(ksT + d*KSTRIDE + js);
                ulonglong2 k1 = *(const ulonglong2*)(ksT + (d+1)*KSTRIDE + js);
                #pragma unroll
                for (int r = 0; r < RPW; r++) {
                    ulonglong2 qq = *(const ulonglong2*)(qs_w + r*32 + d);
                    ffma2(s2[r][0], qq.x, k0.x); ffma2(s2[r][1], qq.x, k0.y);
                    ffma2(s2[r][0], qq.y, k1.x); ffma2(s2[r][1], qq.y, k1.y);
                }
            }
            #pragma unroll
            for (int r = 0; r < RPW; r++) {
                if (r < nrows && vlane) {
                    float s0,s1,sa,sb;
                    f2unpack(s2[r][0], s0, s1);
                    f2unpack(s2[r][1], sa, sb);
                    if (j0+0 >= NTOK) s0 = -1e30f;
                    if (j0+1 >= NTOK) s1 = -1e30f;
                    if (j0+2 >= NTOK) sa = -1e30f;
                    if (j0+3 >= NTOK) sb = -1e30f;
                    rowmax[r] = fmaxf(rowmax[r], fmaxf(fmaxf(s0,s1), fmaxf(sa,sb)));
                    *(float4*)(pw + r*PSTRIDE + j0) = make_float4(s0,s1,sa,sb);
                }
            }
        }
        #pragma unroll
        for (int r = 0; r < RPW; r++) {
            float m = rowmax[r];
            #pragma unroll
            for (int o = 16; o; o >>= 1) m = fmaxf(m, __shfl_xor_sync(0xffffffffu, m, o));
            rowmax[r] = m;
        }
        __syncwarp();

        float rsum[RPW];
        #pragma unroll
        for (int r = 0; r < RPW; r++) rsum[r] = 0.f;
        #pragma unroll
        for (int t = 0; t < 3; t++) {
            int j0 = t*128 + lane*4;
            if (j0 < PSTRIDE) {
                #pragma unroll
                for (int r = 0; r < RPW; r++) {
                    if (r < nrows) {
                        float4 pv = *(float4*)(pw + r*PSTRIDE + j0);
                        pv.x = __expf(pv.x - rowmax[r]);
                        pv.y = __expf(pv.y - rowmax[r]);
                        pv.z = __expf(pv.z - rowmax[r]);
                        pv.w = __expf(pv.w - rowmax[r]);
                        rsum[r] += pv.x + pv.y + pv.z + pv.w;
                        *(float4*)(pw + r*PSTRIDE + j0) = pv;
                    }
                }
            }
        }
        #pragma unroll
        for (int r = 0; r < RPW; r++) {
            float sv = rsum[r];
            #pragma unroll
            for (int o = 16; o; o >>= 1) sv += __shfl_xor_sync(0xffffffffu, sv, o);
            rsum[r] = sv;
        }
        __syncwarp();

        u64t acc2[RPW][2];
        #pragma unroll
        for (int r = 0; r < RPW; r++) { acc2[r][0] = 0ULL; acc2[r][1] = 0ULL; }
        const float* vrow = vsT + lane*KSTRIDE;
        for (int jt = 0; jt < PSTRIDE; jt += 4) {
            ulonglong2 vv = *(const ulonglong2*)(vrow + jt);
            #pragma unroll
            for (int r = 0; r < RPW; r++) {
                ulonglong2 pp = *(const ulonglong2*)(pw + r*PSTRIDE + jt);
                ffma2(acc2[r][0], pp.x, vv.x);
                ffma2(acc2[r][1], pp.y, vv.y);
            }
        }
        #pragma unroll
        for (int r = 0; r < RPW; r++) {
            if (r < nrows) {
                float x0,x1,x2f,x3;
                f2unpack(acc2[r][0], x0, x1);
                f2unpack(acc2[r][1], x2f, x3);
                float o = (x0 + x1 + x2f + x3) / rsum[r];
                size_t oi = ((size_t)b*NTOK + i0 + r)*DIM + h*HD + lane;
                __nv_bfloat16 oh = __float2bfloat16(o);
                __nv_bfloat16 ol = __float2bfloat16(o - __bfloat162float(oh));
                g_aoh[oi] = oh;
                g_aol[oi] = ol;
            }
        }
        __syncwarp();
    }
}

// ============================================================================
// launch
// ============================================================================
extern "C" void kernel_launch(void* const* d_in, const int* in_sizes, int n_in,
                              void* d_out, int out_size)
{
    const float* x      = (const float*)d_in[0];
    const float* mask   = (const float*)d_in[1];
    const float* qkv_w  = (const float*)d_in[2];
    const float* qkv_b  = (const float*)d_in[3];
    const float* proj_w = (const float*)d_in[4];
    const float* proj_b = (const float*)d_in[5];
    const float* rpb    = (const float*)d_in[6];
    const int*   rel    = (const int*)d_in[7];
    float* out = (float*)d_out;

    (void)in_sizes; (void)n_in; (void)out_size;

    const int attn_smem = (64*KSTRIDE + 8*RPW*PSTRIDE + 8*RPW*32*2) * (int)sizeof(float);
    cudaFuncSetAttribute(attn_kernel, cudaFuncAttributeMaxDynamicSharedMemorySize, attn_smem);

    int n4 = MROWS*DIM/4;
    split_x_kernel <<<(n4+255)/256, 256>>>(x, n4);
    split_wq_kernel<<<(DIM*3*DIM+255)/256, 256>>>(qkv_w);
    split_wp_kernel<<<(DIM*DIM+255)/256,   256>>>(proj_w);
    bias_prep<<<dim3(NTOK, NWIN*HEADS), 128>>>(mask, rpb, rel);

    qkv_mma<<<dim3(MROWS/128, 6), 256>>>(qkv_b);
    attn_kernel<<<BATCH*HEADS, 256, attn_smem>>>();
    proj_mma<<<dim3(MROWS/128, 2), 256>>>(proj_b, out);
}

// round 16
// speedup vs baseline: 1.1653x; 1.0038x over previous
#include <cuda_runtime.h>
#include <cuda_bf16.h>

// ---------------- problem constants ----------------
#define BATCH   256
#define NTOK    343
#define DIM     256
#define HEADS   8
#define HD      32
#define NWIN    64
#define SCALE   0.17677669529663687f

#define MROWS   (BATCH*NTOK)           // 87808
#define KSTRIDE 356
#define PSTRIDE 344
#define RPW     8

#define ASTRIDE 40                     // smem row stride in bf16 (80B = 20 banks -> conflict-free)

typedef unsigned long long u64t;
typedef unsigned int u32t;

__device__ __forceinline__ u64t f2pack(float x, float y) {
    u64t r; asm("mov.b64 %0, {%1,%2};" : "=l"(r) : "f"(x), "f"(y)); return r;
}
__device__ __forceinline__ void f2unpack(u64t p, float& x, float& y) {
    asm("mov.b64 {%0,%1}, %2;" : "=f"(x), "=f"(y) : "l"(p));
}
__device__ __forceinline__ void ffma2(u64t& d, u64t a, u64t b) {
    asm("fma.rn.f32x2 %0, %1, %2, %0;" : "+l"(d) : "l"(a), "l"(b));
}

// exp on FMA/ALU pipes (MUFU.EX2 rt=8/SMSP was the attention bottleneck).
// x <= 0 expected; clamp keeps exponent-bit trick in normal range.
__device__ __forceinline__ float fast_exp(float x) {
    x = fmaxf(x, -87.0f);
    float y = x * 1.4426950408889634f;     // log2(e)
    float r = rintf(y);
    float f = y - r;
    float p =        0.0013333558f;        // 2^f Taylor, f in [-0.5, 0.5]
    p = fmaf(p, f,   0.0096181291f);
    p = fmaf(p, f,   0.0555041087f);
    p = fmaf(p, f,   0.2402265070f);
    p = fmaf(p, f,   0.6931471806f);
    p = fmaf(p, f,   1.0f);
    int e = (int)r;
    return __int_as_float(__float_as_int(p) + (e << 23));
}

__device__ __forceinline__ void mma16816(float* c,
        u32t a0, u32t a1, u32t a2, u32t a3, u32t b0, u32t b1)
{
    asm volatile(
        "mma.sync.aligned.m16n8k16.row.col.f32.bf16.bf16.f32 "
        "{%0,%1,%2,%3}, {%4,%5,%6,%7}, {%8,%9}, {%0,%1,%2,%3};"
        : "+f"(c[0]), "+f"(c[1]), "+f"(c[2]), "+f"(c[3])
        : "r"(a0), "r"(a1), "r"(a2), "r"(a3), "r"(b0), "r"(b1));
}

// ---------------- scratch ----------------
__device__ __align__(16) float g_q [BATCH*HEADS*NTOK*HD];
__device__ __align__(16) float g_kT[BATCH*HEADS*HD*NTOK];
__device__ __align__(16) float g_vT[BATCH*HEADS*HD*NTOK];
__device__ __align__(16) float g_bm[(size_t)NWIN*HEADS*NTOK*PSTRIDE];

__device__ __align__(16) __nv_bfloat16 g_xh [MROWS*DIM];
__device__ __align__(16) __nv_bfloat16 g_xl [MROWS*DIM];
__device__ __align__(16) __nv_bfloat16 g_aoh[MROWS*DIM];
__device__ __align__(16) __nv_bfloat16 g_aol[MROWS*DIM];
__device__ __align__(16) __nv_bfloat16 g_wqh[3*DIM*DIM];
__device__ __align__(16) __nv_bfloat16 g_wql[3*DIM*DIM];
__device__ __align__(16) __nv_bfloat16 g_wph[DIM*DIM];
__device__ __align__(16) __nv_bfloat16 g_wpl[DIM*DIM];

// ============================================================================
// split kernels (device symbols referenced in device code only)
// ============================================================================
__global__ __launch_bounds__(256)
void split_x_kernel(const float* __restrict__ X, int n4)
{
    int i = blockIdx.x*blockDim.x + threadIdx.x;
    if (i >= n4) return;
    float4 v = ((const float4*)X)[i];
    __nv_bfloat16 h0 = __float2bfloat16(v.x);
    __nv_bfloat16 h1 = __float2bfloat16(v.y);
    __nv_bfloat16 h2 = __float2bfloat16(v.z);
    __nv_bfloat16 h3 = __float2bfloat16(v.w);
    __nv_bfloat16 l0 = __float2bfloat16(v.x - __bfloat162float(h0));
    __nv_bfloat16 l1 = __float2bfloat16(v.y - __bfloat162float(h1));
    __nv_bfloat16 l2 = __float2bfloat16(v.z - __bfloat162float(h2));
    __nv_bfloat16 l3 = __float2bfloat16(v.w - __bfloat162float(h3));
    __nv_bfloat162* H2 = (__nv_bfloat162*)g_xh;
    __nv_bfloat162* L2 = (__nv_bfloat162*)g_xl;
    H2[2*i]   = __halves2bfloat162(h0, h1);
    H2[2*i+1] = __halves2bfloat162(h2, h3);
    L2[2*i]   = __halves2bfloat162(l0, l1);
    L2[2*i+1] = __halves2bfloat162(l2, l3);
}

__global__ __launch_bounds__(256)
void split_wq_kernel(const float* __restrict__ W)
{
    int idx = blockIdx.x*blockDim.x + threadIdx.x;
    if (idx >= DIM*3*DIM) return;
    float v = W[idx];
    int k = idx / (3*DIM), n = idx - k*(3*DIM);
    __nv_bfloat16 h = __float2bfloat16(v);
    __nv_bfloat16 l = __float2bfloat16(v - __bfloat162float(h));
    g_wqh[(size_t)n*DIM + k] = h;
    g_wql[(size_t)n*DIM + k] = l;
}

__global__ __launch_bounds__(256)
void split_wp_kernel(const float* __restrict__ W)
{
    int idx = blockIdx.x*blockDim.x + threadIdx.x;
    if (idx >= DIM*DIM) return;
    float v = W[idx];
    int k = idx / DIM, n = idx - k*DIM;
    __nv_bfloat16 h = __float2bfloat16(v);
    __nv_bfloat16 l = __float2bfloat16(v - __bfloat162float(h));
    g_wph[(size_t)n*DIM + k] = h;
    g_wpl[(size_t)n*DIM + k] = l;
}

// ============================================================================
// bias+mask prep — one block per (i, w); all 8 heads at once:
// rel_idx + mask read once, table row (8 floats) via two float4 loads.
// ============================================================================
__global__ __launch_bounds__(128)
void bias_prep(const float* __restrict__ mask,
               const float* __restrict__ table,
               const int*   __restrict__ rel)
{
    int i = blockIdx.x;             // 0..342
    int w = blockIdx.y;             // 0..63
    const float* mrow = mask + ((size_t)w*NTOK + i)*NTOK;
    const int*   rrow = rel  + i*NTOK;
    for (int j = threadIdx.x; j < NTOK; j += blockDim.x) {
        int   idx = rrow[j];
        float mv  = mrow[j];
        float4 t0 = *(const float4*)(table + (size_t)idx*HEADS);
        float4 t1 = *(const float4*)(table + (size_t)idx*HEADS + 4);
        float tv[8] = {t0.x,t0.y,t0.z,t0.w,t1.x,t1.y,t1.z,t1.w};
        #pragma unroll
        for (int h = 0; h < 8; h++)
            g_bm[((size_t)(w*HEADS + h)*NTOK + i)*PSTRIDE + j] = mv + tv[h];
    }
}

// ============================================================================
// split-bf16 tensor-core GEMM core (unchanged, verified R15)
// ============================================================================
__device__ __forceinline__ void gemm_bf16_core(
    const __nv_bfloat16* __restrict__ Ah, const __nv_bfloat16* __restrict__ Al,
    const __nv_bfloat16* __restrict__ Bh, const __nv_bfloat16* __restrict__ Bl,
    int m0, int n0, int tid, float cfr[2][8][4],
    __nv_bfloat16* sAh, __nv_bfloat16* sAl,
    __nv_bfloat16* sBh, __nv_bfloat16* sBl)
{
    int lane = tid & 31, warp = tid >> 5;
    int wm = warp >> 1, wn = warp & 1;
    int g = lane >> 2, tig = lane & 3;

    for (int k0 = 0; k0 < DIM; k0 += 32) {
        #pragma unroll
        for (int i = 0; i < 8; i++) {
            int idx = tid + i*256;
            int row = idx & 127;
            int rest = idx >> 7;
            int arr = rest & 3, chunk = rest >> 2;
            const __nv_bfloat16* src;
            __nv_bfloat16* dst;
            if (arr == 0)      { src = Ah + (size_t)(m0+row)*DIM; dst = sAh; }
            else if (arr == 1) { src = Al + (size_t)(m0+row)*DIM; dst = sAl; }
            else if (arr == 2) { src = Bh + (size_t)(n0+row)*DIM; dst = sBh; }
            else               { src = Bl + (size_t)(n0+row)*DIM; dst = sBl; }
            *(uint4*)(dst + row*ASTRIDE + chunk*8) = *(const uint4*)(src + k0 + chunk*8);
        }
        __syncthreads();

        #pragma unroll
        for (int kk = 0; kk < 32; kk += 16) {
            u32t ah[2][4], al[2][4];
            #pragma unroll
            for (int mt = 0; mt < 2; mt++) {
                int mbase = wm*32 + mt*16 + g;
                const __nv_bfloat16* ph = sAh + mbase*ASTRIDE + kk + tig*2;
                const __nv_bfloat16* pl = sAl + mbase*ASTRIDE + kk + tig*2;
                ah[mt][0] = *(const u32t*)(ph);
                ah[mt][1] = *(const u32t*)(ph + 8*ASTRIDE);
                ah[mt][2] = *(const u32t*)(ph + 8);
                ah[mt][3] = *(const u32t*)(ph + 8*ASTRIDE + 8);
                al[mt][0] = *(const u32t*)(pl);
                al[mt][1] = *(const u32t*)(pl + 8*ASTRIDE);
                al[mt][2] = *(const u32t*)(pl + 8);
                al[mt][3] = *(const u32t*)(pl + 8*ASTRIDE + 8);
            }
            #pragma unroll
            for (int nt = 0; nt < 8; nt++) {
                int nbase = wn*64 + nt*8 + g;
                const __nv_bfloat16* qh = sBh + nbase*ASTRIDE + kk + tig*2;
                const __nv_bfloat16* ql = sBl + nbase*ASTRIDE + kk + tig*2;
                u32t bh0 = *(const u32t*)(qh);
                u32t bh1 = *(const u32t*)(qh + 8);
                u32t bl0 = *(const u32t*)(ql);
                u32t bl1 = *(const u32t*)(ql + 8);
                #pragma unroll
                for (int mt = 0; mt < 2; mt++) {
                    mma16816(cfr[mt][nt], ah[mt][0],ah[mt][1],ah[mt][2],ah[mt][3], bh0, bh1);
                    mma16816(cfr[mt][nt], ah[mt][0],ah[mt][1],ah[mt][2],ah[mt][3], bl0, bl1);
                    mma16816(cfr[mt][nt], al[mt][0],al[mt][1],al[mt][2],al[mt][3], bh0, bh1);
                }
            }
        }
        __syncthreads();
    }
}

// ---------------- qkv GEMM: scatter into q/kT/vT ----------------
__device__ __forceinline__ void qkv_store(int m, int col, float v0, float v1,
                                          const float* __restrict__ Bias)
{
    v0 += Bias[col]; v1 += Bias[col+1];
    int bb = m / NTOK;
    int nn = m - bb*NTOK;
    int t3  = col >> 8;
    int rem = col & 255;
    int hh  = rem >> 5;
    int dd  = rem & 31;
    if (t3 == 0) {
        size_t base = (((size_t)bb*HEADS + hh)*NTOK + nn)*HD + dd;
        g_q[base] = v0 * SCALE; g_q[base+1] = v1 * SCALE;
    } else if (t3 == 1) {
        size_t base = (((size_t)bb*HEADS + hh)*HD + dd)*NTOK + nn;
        g_kT[base] = v0; g_kT[base + NTOK] = v1;
    } else {
        size_t base = (((size_t)bb*HEADS + hh)*HD + dd)*NTOK + nn;
        g_vT[base] = v0; g_vT[base + NTOK] = v1;
    }
}

__global__ __launch_bounds__(256)
void qkv_mma(const float* __restrict__ Bias)
{
    __shared__ __align__(16) __nv_bfloat16 sAh[128*ASTRIDE];
    __shared__ __align__(16) __nv_bfloat16 sAl[128*ASTRIDE];
    __shared__ __align__(16) __nv_bfloat16 sBh[128*ASTRIDE];
    __shared__ __align__(16) __nv_bfloat16 sBl[128*ASTRIDE];
    int tid = threadIdx.x;
    int m0 = blockIdx.x * 128, n0 = blockIdx.y * 128;
    float cfr[2][8][4] = {};

    gemm_bf16_core(g_xh, g_xl, g_wqh, g_wql, m0, n0, tid, cfr, sAh, sAl, sBh, sBl);

    int lane = tid & 31, warp = tid >> 5;
    int wm = warp >> 1, wn = warp & 1;
    int g = lane >> 2, tig = lane & 3;
    #pragma unroll
    for (int mt = 0; mt < 2; mt++) {
        int mr = m0 + wm*32 + mt*16 + g;
        #pragma unroll
        for (int nt = 0; nt < 8; nt++) {
            int col = n0 + wn*64 + nt*8 + tig*2;
            float* cc = cfr[mt][nt];
            qkv_store(mr,     col, cc[0], cc[1], Bias);
            qkv_store(mr + 8, col, cc[2], cc[3], Bias);
        }
    }
}

// ---------------- proj GEMM: writes final output ----------------
__global__ __launch_bounds__(256)
void proj_mma(const float* __restrict__ Bias, float* __restrict__ Out)
{
    __shared__ __align__(16) __nv_bfloat16 sAh[128*ASTRIDE];
    __shared__ __align__(16) __nv_bfloat16 sAl[128*ASTRIDE];
    __shared__ __align__(16) __nv_bfloat16 sBh[128*ASTRIDE];
    __shared__ __align__(16) __nv_bfloat16 sBl[128*ASTRIDE];
    int tid = threadIdx.x;
    int m0 = blockIdx.x * 128, n0 = blockIdx.y * 128;
    float cfr[2][8][4] = {};

    gemm_bf16_core(g_aoh, g_aol, g_wph, g_wpl, m0, n0, tid, cfr, sAh, sAl, sBh, sBl);

    int lane = tid & 31, warp = tid >> 5;
    int wm = warp >> 1, wn = warp & 1;
    int g = lane >> 2, tig = lane & 3;
    #pragma unroll
    for (int mt = 0; mt < 2; mt++) {
        int mr = m0 + wm*32 + mt*16 + g;
        #pragma unroll
        for (int nt = 0; nt < 8; nt++) {
            int col = n0 + wn*64 + nt*8 + tig*2;
            float* cc = cfr[mt][nt];
            float b0 = Bias[col], b1 = Bias[col+1];
            *(float2*)(Out + (size_t)mr*DIM + col)     = make_float2(cc[0]+b0, cc[1]+b1);
            *(float2*)(Out + (size_t)(mr+8)*DIM + col) = make_float2(cc[2]+b0, cc[3]+b1);
        }
    }
}

// ============================================================================
// attention — fp32 FFMA2 path, exp moved off MUFU onto FMA/ALU pipes
// ============================================================================
__global__ __launch_bounds__(256)
void attn_kernel()
{
    extern __shared__ float sm[];
    float* ksT  = sm;
    float* vsT  = sm + 32*KSTRIDE;
    float* pbuf = sm + 64*KSTRIDE;
    u64t*  qs   = (u64t*)(sm + 64*KSTRIDE + 8*RPW*PSTRIDE);

    int tid = threadIdx.x, lane = tid & 31, warp = tid >> 5;
    int bh = blockIdx.x;
    int b = bh >> 3, h = bh & 7;
    int w = b & (NWIN-1);

    const float* kg = g_kT + (size_t)bh*HD*NTOK;
    const float* vg = g_vT + (size_t)bh*HD*NTOK;
    for (int idx = tid; idx < 32*KSTRIDE; idx += 256) {
        int d = idx / KSTRIDE, j = idx - d*KSTRIDE;
        float kv = 0.f, vv = 0.f;
        if (j < NTOK) { kv = kg[d*NTOK + j]; vv = vg[d*NTOK + j]; }
        ksT[idx] = kv; vsT[idx] = vv;
    }
    __syncthreads();

    const float* bmh = g_bm + (size_t)(w*HEADS + h)*NTOK*PSTRIDE;
    const float* qg  = g_q  + (size_t)bh*NTOK*HD;
    float* pw   = pbuf + warp*RPW*PSTRIDE;
    u64t*  qs_w = qs   + warp*RPW*32;

    for (int g = warp; g*RPW < NTOK; g += 8) {
        int i0 = g*RPW;
        int nrows = min(RPW, NTOK - i0);

        #pragma unroll
        for (int r = 0; r < RPW; r++) {
            float qv = (r < nrows) ? qg[(i0+r)*HD + lane] : 0.f;
            qs_w[r*32 + lane] = f2pack(qv, qv);
        }
        __syncwarp();

        float rowmax[RPW];
        #pragma unroll
        for (int r = 0; r < RPW; r++) rowmax[r] = -1e30f;

        #pragma unroll
        for (int t = 0; t < 3; t++) {
            int j0 = t*128 + lane*4;
            bool vlane = (j0 < PSTRIDE);
            int js = vlane ? j0 : 0;

            u64t s2[RPW][2];
            #pragma unroll
            for (int r = 0; r < RPW; r++) {
                if (r < nrows) {
                    ulonglong2 bb = *(const ulonglong2*)(bmh + (size_t)(i0+r)*PSTRIDE + js);
                    s2[r][0] = bb.x; s2[r][1] = bb.y;
                } else { s2[r][0] = 0ULL; s2[r][1] = 0ULL; }
            }
            #pragma unroll 4
            for (int d = 0; d < 32; d += 2) {
                ulonglong2 k0 = *(const ulonglong2*)(ksT + d*KSTRIDE + js);
                ulonglong2 k1 = *(const ulonglong2*)(ksT + (d+1)*KSTRIDE + js);
                #pragma unroll
                for (int r = 0; r < RPW; r++) {
                    ulonglong2 qq = *(const ulonglong2*)(qs_w + r*32 + d);
                    ffma2(s2[r][0], qq.x, k0.x); ffma2(s2[r][1], qq.x, k0.y);
                    ffma2(s2[r][0], qq.y, k1.x); ffma2(s2[r][1], qq.y, k1.y);
                }
            }
            #pragma unroll
            for (int r = 0; r < RPW; r++) {
                if (r < nrows && vlane) {
                    float s0,s1,sa,sb;
                    f2unpack(s2[r][0], s0, s1);
                    f2unpack(s2[r][1], sa, sb);
                    if (j0+0 >= NTOK) s0 = -1e30f;
                    if (j0+1 >= NTOK) s1 = -1e30f;
                    if (j0+2 >= NTOK) sa = -1e30f;
                    if (j0+3 >= NTOK) sb = -1e30f;
                    rowmax[r] = fmaxf(rowmax[r], fmaxf(fmaxf(s0,s1), fmaxf(sa,sb)));
                    *(float4*)(pw + r*PSTRIDE + j0) = make_float4(s0,s1,sa,sb);
                }
            }
        }
        #pragma unroll
        for (int r = 0; r < RPW; r++) {
            float m = rowmax[r];
            #pragma unroll
            for (int o = 16; o; o >>= 1) m = fmaxf(m, __shfl_xor_sync(0xffffffffu, m, o));
            rowmax[r] = m;
        }
        __syncwarp();

        float rsum[RPW];
        #pragma unroll
        for (int r = 0; r < RPW; r++) rsum[r] = 0.f;
        #pragma unroll
        for (int t = 0; t < 3; t++) {
            int j0 = t*128 + lane*4;
            if (j0 < PSTRIDE) {
                #pragma unroll
                for (int r = 0; r < RPW; r++) {
                    if (r < nrows) {
                        float4 pv = *(float4*)(pw + r*PSTRIDE + j0);
                        pv.x = fast_exp(pv.x - rowmax[r]);
                        pv.y = fast_exp(pv.y - rowmax[r]);
                        pv.z = fast_exp(pv.z - rowmax[r]);
                        pv.w = fast_exp(pv.w - rowmax[r]);
                        rsum[r] += pv.x + pv.y + pv.z + pv.w;
                        *(float4*)(pw + r*PSTRIDE + j0) = pv;
                    }
                }
            }
        }
        #pragma unroll
        for (int r = 0; r < RPW; r++) {
            float sv = rsum[r];
            #pragma unroll
            for (int o = 16; o; o >>= 1) sv += __shfl_xor_sync(0xffffffffu, sv, o);
            rsum[r] = sv;
        }
        __syncwarp();

        u64t acc2[RPW][2];
        #pragma unroll
        for (int r = 0; r < RPW; r++) { acc2[r][0] = 0ULL; acc2[r][1] = 0ULL; }
        const float* vrow = vsT + lane*KSTRIDE;
        for (int jt = 0; jt < PSTRIDE; jt += 4) {
            ulonglong2 vv = *(const ulonglong2*)(vrow + jt);
            #pragma unroll
            for (int r = 0; r < RPW; r++) {
                ulonglong2 pp = *(const ulonglong2*)(pw + r*PSTRIDE + jt);
                ffma2(acc2[r][0], pp.x, vv.x);
                ffma2(acc2[r][1], pp.y, vv.y);
            }
        }
        #pragma unroll
        for (int r = 0; r < RPW; r++) {
            if (r < nrows) {
                float x0,x1,x2f,x3;
                f2unpack(acc2[r][0], x0, x1);
                f2unpack(acc2[r][1], x2f, x3);
                float o = (x0 + x1 + x2f + x3) / rsum[r];
                size_t oi = ((size_t)b*NTOK + i0 + r)*DIM + h*HD + lane;
                __nv_bfloat16 oh = __float2bfloat16(o);
                __nv_bfloat16 ol = __float2bfloat16(o - __bfloat162float(oh));
                g_aoh[oi] = oh;
                g_aol[oi] = ol;
            }
        }
        __syncwarp();
    }
}

// ============================================================================
// launch
// ============================================================================
extern "C" void kernel_launch(void* const* d_in, const int* in_sizes, int n_in,
                              void* d_out, int out_size)
{
    const float* x      = (const float*)d_in[0];
    const float* mask   = (const float*)d_in[1];
    const float* qkv_w  = (const float*)d_in[2];
    const float* qkv_b  = (const float*)d_in[3];
    const float* proj_w = (const float*)d_in[4];
    const float* proj_b = (const float*)d_in[5];
    const float* rpb    = (const float*)d_in[6];
    const int*   rel    = (const int*)d_in[7];
    float* out = (float*)d_out;

    (void)in_sizes; (void)n_in; (void)out_size;

    const int attn_smem = (64*KSTRIDE + 8*RPW*PSTRIDE + 8*RPW*32*2) * (int)sizeof(float);
    cudaFuncSetAttribute(attn_kernel, cudaFuncAttributeMaxDynamicSharedMemorySize, attn_smem);

    int n4 = MROWS*DIM/4;
    split_x_kernel <<<(n4+255)/256, 256>>>(x, n4);
    split_wq_kernel<<<(DIM*3*DIM+255)/256, 256>>>(qkv_w);
    split_wp_kernel<<<(DIM*DIM+255)/256,   256>>>(proj_w);
    bias_prep<<<dim3(NTOK, NWIN), 128>>>(mask, rpb, rel);

    qkv_mma<<<dim3(MROWS/128, 6), 256>>>(qkv_b);
    attn_kernel<<<BATCH*HEADS, 256, attn_smem>>>();
    proj_mma<<<dim3(MROWS/128, 2), 256>>>(proj_b, out);
}

// round 17
// speedup vs baseline: 1.8186x; 1.5606x over previous
#include <cuda_runtime.h>
#include <cuda_bf16.h>

// ---------------- problem constants ----------------
#define BATCH   256
#define NTOK    343
#define DIM     256
#define HEADS   8
#define HD      32
#define NWIN    64
#define SCALE   0.17677669529663687f

#define MROWS   (BATCH*NTOK)           // 87808
#define PSTRIDE 352                    // bias row stride; cols 343..351 = -1e30
#define NTOKP   352                    // padded tokens = 22*16
#define KSTR    40                     // k smem row stride (bf16): 80B, banks 20g%32 distinct
#define VSTR    352                    // vT smem row stride (tokens): 704B, banks 12g%32 distinct
#define VGSTR   344                    // vT gmem row stride

#define ASTRIDE 40                     // GEMM smem stride (bf16)

typedef unsigned long long u64t;
typedef unsigned int u32t;

// exp on FMA/ALU pipes
__device__ __forceinline__ float fast_exp(float x) {
    x = fmaxf(x, -87.0f);
    float y = x * 1.4426950408889634f;
    float r = rintf(y);
    float f = y - r;
    float p =        0.0013333558f;
    p = fmaf(p, f,   0.0096181291f);
    p = fmaf(p, f,   0.0555041087f);
    p = fmaf(p, f,   0.2402265070f);
    p = fmaf(p, f,   0.6931471806f);
    p = fmaf(p, f,   1.0f);
    int e = (int)r;
    return __int_as_float(__float_as_int(p) + (e << 23));
}

__device__ __forceinline__ void mma16816(float* c,
        u32t a0, u32t a1, u32t a2, u32t a3, u32t b0, u32t b1)
{
    asm volatile(
        "mma.sync.aligned.m16n8k16.row.col.f32.bf16.bf16.f32 "
        "{%0,%1,%2,%3}, {%4,%5,%6,%7}, {%8,%9}, {%0,%1,%2,%3};"
        : "+f"(c[0]), "+f"(c[1]), "+f"(c[2]), "+f"(c[3])
        : "r"(a0), "r"(a1), "r"(a2), "r"(a3), "r"(b0), "r"(b1));
}

// split (a,b) into packed bf16x2 hi + lo
__device__ __forceinline__ void bsplit2(float a, float b, u32t& hi, u32t& lo) {
    __nv_bfloat16 ah = __float2bfloat16(a), bh = __float2bfloat16(b);
    __nv_bfloat16 al = __float2bfloat16(a - __bfloat162float(ah));
    __nv_bfloat16 bl = __float2bfloat16(b - __bfloat162float(bh));
    __nv_bfloat162 th = __halves2bfloat162(ah, bh);
    __nv_bfloat162 tl = __halves2bfloat162(al, bl);
    hi = *reinterpret_cast<u32t*>(&th);
    lo = *reinterpret_cast<u32t*>(&tl);
}

__device__ __forceinline__ float qmax(float x) {
    x = fmaxf(x, __shfl_xor_sync(0xffffffffu, x, 1));
    x = fmaxf(x, __shfl_xor_sync(0xffffffffu, x, 2));
    return x;
}
__device__ __forceinline__ float qsum(float x) {
    x += __shfl_xor_sync(0xffffffffu, x, 1);
    x += __shfl_xor_sync(0xffffffffu, x, 2);
    return x;
}

// ---------------- scratch ----------------
__device__ __align__(16) float g_bm[(size_t)NWIN*HEADS*NTOK*PSTRIDE];

__device__ __align__(16) __nv_bfloat16 g_qh [BATCH*HEADS*NTOK*HD];   // q split (scaled), [bh][n][d]
__device__ __align__(16) __nv_bfloat16 g_ql [BATCH*HEADS*NTOK*HD];
__device__ __align__(16) __nv_bfloat16 g_kh [BATCH*HEADS*NTOK*HD];   // k split, [bh][n][d]
__device__ __align__(16) __nv_bfloat16 g_kl [BATCH*HEADS*NTOK*HD];
__device__ __align__(16) __nv_bfloat16 g_vth[BATCH*HEADS*HD*VGSTR];  // vT split, [bh][d][n]
__device__ __align__(16) __nv_bfloat16 g_vtl[BATCH*HEADS*HD*VGSTR];

__device__ __align__(16) __nv_bfloat16 g_xh [MROWS*DIM];
__device__ __align__(16) __nv_bfloat16 g_xl [MROWS*DIM];
__device__ __align__(16) __nv_bfloat16 g_aoh[MROWS*DIM];
__device__ __align__(16) __nv_bfloat16 g_aol[MROWS*DIM];
__device__ __align__(16) __nv_bfloat16 g_wqh[3*DIM*DIM];
__device__ __align__(16) __nv_bfloat16 g_wql[3*DIM*DIM];
__device__ __align__(16) __nv_bfloat16 g_wph[DIM*DIM];
__device__ __align__(16) __nv_bfloat16 g_wpl[DIM*DIM];

// ============================================================================
// split kernels
// ============================================================================
__global__ __launch_bounds__(256)
void split_x_kernel(const float* __restrict__ X, int n4)
{
    int i = blockIdx.x*blockDim.x + threadIdx.x;
    if (i >= n4) return;
    float4 v = ((const float4*)X)[i];
    u32t h01, l01, h23, l23;
    bsplit2(v.x, v.y, h01, l01);
    bsplit2(v.z, v.w, h23, l23);
    ((u32t*)g_xh)[2*i]   = h01;  ((u32t*)g_xh)[2*i+1] = h23;
    ((u32t*)g_xl)[2*i]   = l01;  ((u32t*)g_xl)[2*i+1] = l23;
}

__global__ __launch_bounds__(256)
void split_wq_kernel(const float* __restrict__ W)
{
    int idx = blockIdx.x*blockDim.x + threadIdx.x;
    if (idx >= DIM*3*DIM) return;
    float v = W[idx];
    int k = idx / (3*DIM), n = idx - k*(3*DIM);
    __nv_bfloat16 h = __float2bfloat16(v);
    g_wqh[(size_t)n*DIM + k] = h;
    g_wql[(size_t)n*DIM + k] = __float2bfloat16(v - __bfloat162float(h));
}

__global__ __launch_bounds__(256)
void split_wp_kernel(const float* __restrict__ W)
{
    int idx = blockIdx.x*blockDim.x + threadIdx.x;
    if (idx >= DIM*DIM) return;
    float v = W[idx];
    int k = idx / DIM, n = idx - k*DIM;
    __nv_bfloat16 h = __float2bfloat16(v);
    g_wph[(size_t)n*DIM + k] = h;
    g_wpl[(size_t)n*DIM + k] = __float2bfloat16(v - __bfloat162float(h));
}

// ============================================================================
// bias+mask prep — pads cols 343..351 with -1e30 (masks padded keys)
// ============================================================================
__global__ __launch_bounds__(128)
void bias_prep(const float* __restrict__ mask,
               const float* __restrict__ table,
               const int*   __restrict__ rel)
{
    int i = blockIdx.x;             // 0..342
    int w = blockIdx.y;             // 0..63
    const float* mrow = mask + ((size_t)w*NTOK + i)*NTOK;
    const int*   rrow = rel  + i*NTOK;
    for (int j = threadIdx.x; j < PSTRIDE; j += blockDim.x) {
        if (j < NTOK) {
            int   idx = rrow[j];
            float mv  = mrow[j];
            float4 t0 = *(const float4*)(table + (size_t)idx*HEADS);
            float4 t1 = *(const float4*)(table + (size_t)idx*HEADS + 4);
            float tv[8] = {t0.x,t0.y,t0.z,t0.w,t1.x,t1.y,t1.z,t1.w};
            #pragma unroll
            for (int h = 0; h < 8; h++)
                g_bm[((size_t)(w*HEADS + h)*NTOK + i)*PSTRIDE + j] = mv + tv[h];
        } else {
            #pragma unroll
            for (int h = 0; h < 8; h++)
                g_bm[((size_t)(w*HEADS + h)*NTOK + i)*PSTRIDE + j] = -1e30f;
        }
    }
}

// ============================================================================
// split-bf16 tensor-core GEMM core (verified R15)
// ============================================================================
__device__ __forceinline__ void gemm_bf16_core(
    const __nv_bfloat16* __restrict__ Ah, const __nv_bfloat16* __restrict__ Al,
    const __nv_bfloat16* __restrict__ Bh, const __nv_bfloat16* __restrict__ Bl,
    int m0, int n0, int tid, float cfr[2][8][4],
    __nv_bfloat16* sAh, __nv_bfloat16* sAl,
    __nv_bfloat16* sBh, __nv_bfloat16* sBl)
{
    int lane = tid & 31, warp = tid >> 5;
    int wm = warp >> 1, wn = warp & 1;
    int g = lane >> 2, tig = lane & 3;

    for (int k0 = 0; k0 < DIM; k0 += 32) {
        #pragma unroll
        for (int i = 0; i < 8; i++) {
            int idx = tid + i*256;
            int row = idx & 127;
            int rest = idx >> 7;
            int arr = rest & 3, chunk = rest >> 2;
            const __nv_bfloat16* src;
            __nv_bfloat16* dst;
            if (arr == 0)      { src = Ah + (size_t)(m0+row)*DIM; dst = sAh; }
            else if (arr == 1) { src = Al + (size_t)(m0+row)*DIM; dst = sAl; }
            else if (arr == 2) { src = Bh + (size_t)(n0+row)*DIM; dst = sBh; }
            else               { src = Bl + (size_t)(n0+row)*DIM; dst = sBl; }
            *(uint4*)(dst + row*ASTRIDE + chunk*8) = *(const uint4*)(src + k0 + chunk*8);
        }
        __syncthreads();

        #pragma unroll
        for (int kk = 0; kk < 32; kk += 16) {
            u32t ah[2][4], al[2][4];
            #pragma unroll
            for (int mt = 0; mt < 2; mt++) {
                int mbase = wm*32 + mt*16 + g;
                const __nv_bfloat16* ph = sAh + mbase*ASTRIDE + kk + tig*2;
                const __nv_bfloat16* pl = sAl + mbase*ASTRIDE + kk + tig*2;
                ah[mt][0] = *(const u32t*)(ph);
                ah[mt][1] = *(const u32t*)(ph + 8*ASTRIDE);
                ah[mt][2] = *(const u32t*)(ph + 8);
                ah[mt][3] = *(const u32t*)(ph + 8*ASTRIDE + 8);
                al[mt][0] = *(const u32t*)(pl);
                al[mt][1] = *(const u32t*)(pl + 8*ASTRIDE);
                al[mt][2] = *(const u32t*)(pl + 8);
                al[mt][3] = *(const u32t*)(pl + 8*ASTRIDE + 8);
            }
            #pragma unroll
            for (int nt = 0; nt < 8; nt++) {
                int nbase = wn*64 + nt*8 + g;
                const __nv_bfloat16* qh = sBh + nbase*ASTRIDE + kk + tig*2;
                const __nv_bfloat16* ql = sBl + nbase*ASTRIDE + kk + tig*2;
                u32t bh0 = *(const u32t*)(qh);
                u32t bh1 = *(const u32t*)(qh + 8);
                u32t bl0 = *(const u32t*)(ql);
                u32t bl1 = *(const u32t*)(ql + 8);
                #pragma unroll
                for (int mt = 0; mt < 2; mt++) {
                    mma16816(cfr[mt][nt], ah[mt][0],ah[mt][1],ah[mt][2],ah[mt][3], bh0, bh1);
                    mma16816(cfr[mt][nt], ah[mt][0],ah[mt][1],ah[mt][2],ah[mt][3], bl0, bl1);
                    mma16816(cfr[mt][nt], al[mt][0],al[mt][1],al[mt][2],al[mt][3], bh0, bh1);
                }
            }
        }
        __syncthreads();
    }
}

// ---------------- qkv GEMM: scatter into split-bf16 q/k/vT ----------------
__device__ __forceinline__ void qkv_store(int m, int col, float v0, float v1,
                                          const float* __restrict__ Bias)
{
    v0 += Bias[col]; v1 += Bias[col+1];
    int bb = m / NTOK;
    int nn = m - bb*NTOK;
    int t3  = col >> 8;
    int rem = col & 255;
    int hh  = rem >> 5;
    int dd  = rem & 31;            // even (col = ... + tig*2)
    int bh  = bb*HEADS + hh;
    if (t3 == 0) {
        u32t hi, lo; bsplit2(v0*SCALE, v1*SCALE, hi, lo);
        size_t base = ((size_t)bh*NTOK + nn)*HD + dd;
        *(u32t*)(g_qh + base) = hi;
        *(u32t*)(g_ql + base) = lo;
    } else if (t3 == 1) {
        u32t hi, lo; bsplit2(v0, v1, hi, lo);
        size_t base = ((size_t)bh*NTOK + nn)*HD + dd;
        *(u32t*)(g_kh + base) = hi;
        *(u32t*)(g_kl + base) = lo;
    } else {
        __nv_bfloat16 h0 = __float2bfloat16(v0);
        __nv_bfloat16 h1 = __float2bfloat16(v1);
        size_t b0 = ((size_t)bh*HD + dd)*VGSTR + nn;
        size_t b1 = ((size_t)bh*HD + dd + 1)*VGSTR + nn;
        g_vth[b0] = h0; g_vtl[b0] = __float2bfloat16(v0 - __bfloat162float(h0));
        g_vth[b1] = h1; g_vtl[b1] = __float2bfloat16(v1 - __bfloat162float(h1));
    }
}

__global__ __launch_bounds__(256)
void qkv_mma(const float* __restrict__ Bias)
{
    __shared__ __align__(16) __nv_bfloat16 sAh[128*ASTRIDE];
    __shared__ __align__(16) __nv_bfloat16 sAl[128*ASTRIDE];
    __shared__ __align__(16) __nv_bfloat16 sBh[128*ASTRIDE];
    __shared__ __align__(16) __nv_bfloat16 sBl[128*ASTRIDE];
    int tid = threadIdx.x;
    int m0 = blockIdx.x * 128, n0 = blockIdx.y * 128;
    float cfr[2][8][4] = {};

    gemm_bf16_core(g_xh, g_xl, g_wqh, g_wql, m0, n0, tid, cfr, sAh, sAl, sBh, sBl);

    int lane = tid & 31, warp = tid >> 5;
    int wm = warp >> 1, wn = warp & 1;
    int g = lane >> 2, tig = lane & 3;
    #pragma unroll
    for (int mt = 0; mt < 2; mt++) {
        int mr = m0 + wm*32 + mt*16 + g;
        #pragma unroll
        for (int nt = 0; nt < 8; nt++) {
            int col = n0 + wn*64 + nt*8 + tig*2;
            float* cc = cfr[mt][nt];
            qkv_store(mr,     col, cc[0], cc[1], Bias);
            qkv_store(mr + 8, col, cc[2], cc[3], Bias);
        }
    }
}

// ---------------- proj GEMM ----------------
__global__ __launch_bounds__(256)
void proj_mma(const float* __restrict__ Bias, float* __restrict__ Out)
{
    __shared__ __align__(16) __nv_bfloat16 sAh[128*ASTRIDE];
    __shared__ __align__(16) __nv_bfloat16 sAl[128*ASTRIDE];
    __shared__ __align__(16) __nv_bfloat16 sBh[128*ASTRIDE];
    __shared__ __align__(16) __nv_bfloat16 sBl[128*ASTRIDE];
    int tid = threadIdx.x;
    int m0 = blockIdx.x * 128, n0 = blockIdx.y * 128;
    float cfr[2][8][4] = {};

    gemm_bf16_core(g_aoh, g_aol, g_wph, g_wpl, m0, n0, tid, cfr, sAh, sAl, sBh, sBl);

    int lane = tid & 31, warp = tid >> 5;
    int wm = warp >> 1, wn = warp & 1;
    int g = lane >> 2, tig = lane & 3;
    #pragma unroll
    for (int mt = 0; mt < 2; mt++) {
        int mr = m0 + wm*32 + mt*16 + g;
        #pragma unroll
        for (int nt = 0; nt < 8; nt++) {
            int col = n0 + wn*64 + nt*8 + tig*2;
            float* cc = cfr[mt][nt];
            float b0 = Bias[col], b1 = Bias[col+1];
            *(float2*)(Out + (size_t)mr*DIM + col)     = make_float2(cc[0]+b0, cc[1]+b1);
            *(float2*)(Out + (size_t)(mr+8)*DIM + col) = make_float2(cc[2]+b0, cc[3]+b1);
        }
    }
}

// ============================================================================
// attention — HMMA flash style. 1 block / (window,head), 8 warps,
// each warp owns 16-row query tiles, online softmax, no score buffer.
// ============================================================================
__global__ __launch_bounds__(256, 2)
void attn_kernel()
{
    extern __shared__ __align__(16) __nv_bfloat16 smb[];
    __nv_bfloat16* ksH = smb;                    // [352][KSTR]
    __nv_bfloat16* ksL = smb + NTOKP*KSTR;
    __nv_bfloat16* vtH = smb + 2*NTOKP*KSTR;     // [32][VSTR]
    __nv_bfloat16* vtL = smb + 2*NTOKP*KSTR + HD*VSTR;

    int tid = threadIdx.x, lane = tid & 31, warp = tid >> 5;
    int g = lane >> 2, tig = lane & 3;
    int bh = blockIdx.x;
    int b = bh >> 3, h = bh & 7;
    int w = b & (NWIN-1);

    // ---- fill smem: k [352][32] (rows >=343 zero), vT [32][352] (cols >=344 zero)
    {
        const __nv_bfloat16* kh = g_kh + (size_t)bh*NTOK*HD;
        const __nv_bfloat16* kl = g_kl + (size_t)bh*NTOK*HD;
        for (int idx = tid; idx < NTOKP*4; idx += 256) {
            int row = idx >> 2, ch = idx & 3;
            uint4 vh = make_uint4(0,0,0,0), vl = make_uint4(0,0,0,0);
            if (row < NTOK) {
                vh = *(const uint4*)(kh + (size_t)row*HD + ch*8);
                vl = *(const uint4*)(kl + (size_t)row*HD + ch*8);
            }
            *(uint4*)(ksH + row*KSTR + ch*8) = vh;
            *(uint4*)(ksL + row*KSTR + ch*8) = vl;
        }
        const __nv_bfloat16* vh_ = g_vth + (size_t)bh*HD*VGSTR;
        const __nv_bfloat16* vl_ = g_vtl + (size_t)bh*HD*VGSTR;
        for (int idx = tid; idx < HD*44; idx += 256) {
            int d = idx / 44, ch = idx - d*44;
            uint4 vh = make_uint4(0,0,0,0), vl = make_uint4(0,0,0,0);
            if (ch < 43) {
                vh = *(const uint4*)(vh_ + (size_t)d*VGSTR + ch*8);
                vl = *(const uint4*)(vl_ + (size_t)d*VGSTR + ch*8);
            }
            *(uint4*)(vtH + d*VSTR + ch*8) = vh;
            *(uint4*)(vtL + d*VSTR + ch*8) = vl;
        }
    }
    __syncthreads();

    const float* bmh = g_bm + (size_t)(w*HEADS + h)*NTOK*PSTRIDE;
    const __nv_bfloat16* qhp = g_qh + (size_t)bh*NTOK*HD;
    const __nv_bfloat16* qlp = g_ql + (size_t)bh*NTOK*HD;

    for (int tile = warp; tile < NTOKP/16; tile += 8) {
        int r0 = tile*16;
        int rg  = min(r0 + g,     NTOK-1);
        int rg8 = min(r0 + 8 + g, NTOK-1);

        // q A-frags (held for whole tile)
        u32t aH[2][4], aL[2][4];
        #pragma unroll
        for (int kt = 0; kt < 2; kt++) {
            int d0 = kt*16 + 2*tig;
            aH[kt][0] = *(const u32t*)(qhp + (size_t)rg *HD + d0);
            aH[kt][1] = *(const u32t*)(qhp + (size_t)rg8*HD + d0);
            aH[kt][2] = *(const u32t*)(qhp + (size_t)rg *HD + d0 + 8);
            aH[kt][3] = *(const u32t*)(qhp + (size_t)rg8*HD + d0 + 8);
            aL[kt][0] = *(const u32t*)(qlp + (size_t)rg *HD + d0);
            aL[kt][1] = *(const u32t*)(qlp + (size_t)rg8*HD + d0);
            aL[kt][2] = *(const u32t*)(qlp + (size_t)rg *HD + d0 + 8);
            aL[kt][3] = *(const u32t*)(qlp + (size_t)rg8*HD + d0 + 8);
        }

        float O[4][4] = {};
        float m0r = -1e30f, m1r = -1e30f;
        float l0r = 0.f,    l1r = 0.f;

        for (int kb = 0; kb < NTOKP; kb += 16) {
            float c[2][4] = {};
            // ---- S = q k^T
            #pragma unroll
            for (int e = 0; e < 2; e++) {
                int key = kb + e*8 + g;
                #pragma unroll
                for (int kt = 0; kt < 2; kt++) {
                    int d0 = kt*16 + 2*tig;
                    u32t bh0 = *(const u32t*)(ksH + key*KSTR + d0);
                    u32t bh1 = *(const u32t*)(ksH + key*KSTR + d0 + 8);
                    u32t bl0 = *(const u32t*)(ksL + key*KSTR + d0);
                    u32t bl1 = *(const u32t*)(ksL + key*KSTR + d0 + 8);
                    mma16816(c[e], aH[kt][0],aH[kt][1],aH[kt][2],aH[kt][3], bh0, bh1);
                    mma16816(c[e], aH[kt][0],aH[kt][1],aH[kt][2],aH[kt][3], bl0, bl1);
                    mma16816(c[e], aL[kt][0],aL[kt][1],aL[kt][2],aL[kt][3], bh0, bh1);
                }
            }
            // ---- + bias (padding cols carry -1e30)
            #pragma unroll
            for (int e = 0; e < 2; e++) {
                int jc = kb + e*8 + 2*tig;
                float2 bz0 = *(const float2*)(bmh + (size_t)rg *PSTRIDE + jc);
                float2 bz1 = *(const float2*)(bmh + (size_t)rg8*PSTRIDE + jc);
                c[e][0] += bz0.x; c[e][1] += bz0.y;
                c[e][2] += bz1.x; c[e][3] += bz1.y;
            }
            // ---- online softmax
            float tm0 = fmaxf(fmaxf(c[0][0],c[0][1]), fmaxf(c[1][0],c[1][1]));
            float tm1 = fmaxf(fmaxf(c[0][2],c[0][3]), fmaxf(c[1][2],c[1][3]));
            tm0 = qmax(tm0); tm1 = qmax(tm1);
            float mn0 = fmaxf(m0r, tm0), mn1 = fmaxf(m1r, tm1);
            float al0 = fast_exp(m0r - mn0), al1 = fast_exp(m1r - mn1);
            m0r = mn0; m1r = mn1;
            float p[2][4];
            #pragma unroll
            for (int e = 0; e < 2; e++) {
                p[e][0] = fast_exp(c[e][0] - mn0);
                p[e][1] = fast_exp(c[e][1] - mn0);
                p[e][2] = fast_exp(c[e][2] - mn1);
                p[e][3] = fast_exp(c[e][3] - mn1);
            }
            float s0 = p[0][0]+p[0][1]+p[1][0]+p[1][1];
            float s1 = p[0][2]+p[0][3]+p[1][2]+p[1][3];
            s0 = qsum(s0); s1 = qsum(s1);
            l0r = l0r*al0 + s0;
            l1r = l1r*al1 + s1;
            #pragma unroll
            for (int f = 0; f < 4; f++) {
                O[f][0] *= al0; O[f][1] *= al0;
                O[f][2] *= al1; O[f][3] *= al1;
            }
            // ---- p -> A-frags (register remap, no smem)
            u32t pH[4], pL[4];
            bsplit2(p[0][0], p[0][1], pH[0], pL[0]);   // row g,   k 2tig,2tig+1
            bsplit2(p[0][2], p[0][3], pH[1], pL[1]);   // row g+8
            bsplit2(p[1][0], p[1][1], pH[2], pL[2]);   // row g,   k 8+2tig
            bsplit2(p[1][2], p[1][3], pH[3], pL[3]);   // row g+8
            // ---- O += P V
            #pragma unroll
            for (int f = 0; f < 4; f++) {
                int d = f*8 + g;
                u32t vh0 = *(const u32t*)(vtH + d*VSTR + kb + 2*tig);
                u32t vh1 = *(const u32t*)(vtH + d*VSTR + kb + 8 + 2*tig);
                u32t vl0 = *(const u32t*)(vtL + d*VSTR + kb + 2*tig);
                u32t vl1 = *(const u32t*)(vtL + d*VSTR + kb + 8 + 2*tig);
                mma16816(O[f], pH[0],pH[1],pH[2],pH[3], vh0, vh1);
                mma16816(O[f], pH[0],pH[1],pH[2],pH[3], vl0, vl1);
                mma16816(O[f], pL[0],pL[1],pL[2],pL[3], vh0, vh1);
            }
        }

        // ---- write O / l (split bf16 for proj)
        float rl0 = 1.f / l0r, rl1 = 1.f / l1r;
        int row0 = r0 + g, row1 = r0 + 8 + g;
        #pragma unroll
        for (int f = 0; f < 4; f++) {
            int col = h*HD + f*8 + 2*tig;
            if (row0 < NTOK) {
                u32t hi, lo; bsplit2(O[f][0]*rl0, O[f][1]*rl0, hi, lo);
                size_t base = ((size_t)b*NTOK + row0)*DIM + col;
                *(u32t*)(g_aoh + base) = hi;
                *(u32t*)(g_aol + base) = lo;
            }
            if (row1 < NTOK) {
                u32t hi, lo; bsplit2(O[f][2]*rl1, O[f][3]*rl1, hi, lo);
                size_t base = ((size_t)b*NTOK + row1)*DIM + col;
                *(u32t*)(g_aoh + base) = hi;
                *(u32t*)(g_aol + base) = lo;
            }
        }
    }
}

// ============================================================================
// launch
// ============================================================================
extern "C" void kernel_launch(void* const* d_in, const int* in_sizes, int n_in,
                              void* d_out, int out_size)
{
    const float* x      = (const float*)d_in[0];
    const float* mask   = (const float*)d_in[1];
    const float* qkv_w  = (const float*)d_in[2];
    const float* qkv_b  = (const float*)d_in[3];
    const float* proj_w = (const float*)d_in[4];
    const float* proj_b = (const float*)d_in[5];
    const float* rpb    = (const float*)d_in[6];
    const int*   rel    = (const int*)d_in[7];
    float* out = (float*)d_out;

    (void)in_sizes; (void)n_in; (void)out_size;

    const int attn_smem = (2*NTOKP*KSTR + 2*HD*VSTR) * 2;   // 101376 B
    cudaFuncSetAttribute(attn_kernel, cudaFuncAttributeMaxDynamicSharedMemorySize, attn_smem);

    int n4 = MROWS*DIM/4;
    split_x_kernel <<<(n4+255)/256, 256>>>(x, n4);
    split_wq_kernel<<<(DIM*3*DIM+255)/256, 256>>>(qkv_w);
    split_wp_kernel<<<(DIM*DIM+255)/256,   256>>>(proj_w);
    bias_prep<<<dim3(NTOK, NWIN), 128>>>(mask, rpb, rel);

    qkv_mma<<<dim3(MROWS/128, 6), 256>>>(qkv_b);
    attn_kernel<<<BATCH*HEADS, 256, attn_smem>>>();
    proj_mma<<<dim3(MROWS/128, 2), 256>>>(proj_b, out);
}